// round 1
// baseline (speedup 1.0000x reference)
#include <cuda_runtime.h>
#include <math_constants.h>
#include <math.h>

#define CDIM     64
#define NCODES   1024
#define KTOT     2048
#define BATCH    32
#define N_VEC    (BATCH * KTOT)          // 65536
#define Z_ELEMS  (BATCH * CDIM * KTOT)   // 4194304
#define BVEC     128                     // vectors per block
#define BCODE    128                     // codes per chunk
#define NCHUNK   (NCODES / BCODE)        // 8
#define EPITCH   132                     // padded code pitch in smem

// smem layout (floats): zs[64*128] | zzs[128] | es[64*132]
#define ZS_FLOATS   (CDIM * BVEC)            // 8192
#define ES_FLOATS   (CDIM * EPITCH)          // 8448
#define SMEM_FLOATS (ZS_FLOATS + BVEC + ES_FLOATS)
#define SMEM_BYTES  (SMEM_FLOATS * 4)        // 67072

__device__ float  g_ee[NCODES];
__device__ int    g_hist[NCODES];
__device__ double g_loss;

// ---------------------------------------------------------------------------
// prep: codebook norms, zero histogram + loss accumulator (graph-replay safe)
// ---------------------------------------------------------------------------
__global__ void vq_prep(const float* __restrict__ cb) {
    int j = blockIdx.x * blockDim.x + threadIdx.x;
    if (j < NCODES) {
        const float* row = cb + j * CDIM;
        float s = 0.f;
#pragma unroll
        for (int c = 0; c < CDIM; ++c) {
            // unfused: product rounded, then added (match jnp sum(e*e))
            float p = __fmul_rn(row[c], row[c]);
            s = __fadd_rn(s, p);
        }
        g_ee[j]   = s;
        g_hist[j] = 0;
    }
    if (j == 0) g_loss = 0.0;
}

// ---------------------------------------------------------------------------
// main: distances + argmin + gather + outputs
// grid = (KTOT/BVEC, BATCH) = (16, 32), block = 256
// ---------------------------------------------------------------------------
__global__ __launch_bounds__(256, 1)
void vq_main(const float* __restrict__ z_e, const float* __restrict__ cb,
             float* __restrict__ out) {
    extern __shared__ float sm[];
    float* zs  = sm;                       // [c][v]  (64 x 128)
    float* zzs = sm + ZS_FLOATS;           // [v]
    float* es  = sm + ZS_FLOATS + BVEC;    // [c][code] pitch 132
    // reduction arrays reuse es after mainloop
    float* rd  = es;                       // [tx][v] 16*128
    int*   ri  = (int*)(es + 16 * BVEC);   // [tx][v] 16*128

    const int tid = threadIdx.x;
    const int b   = blockIdx.y;
    const int k0  = blockIdx.x * BVEC;

    // --- load z tile: zs[c][v] = z_e[b][c][k0+v]  (coalesced) ---
    const float* zbase = z_e + ((size_t)b * CDIM) * KTOT + k0;
#pragma unroll
    for (int i = 0; i < ZS_FLOATS / 256; ++i) {
        int idx = tid + i * 256;
        int c = idx >> 7, v = idx & 127;
        zs[idx] = zbase[(size_t)c * KTOT + v];
    }
    __syncthreads();

    // --- per-vector squared norm (unfused, matching reference rounding style) ---
    if (tid < BVEC) {
        float s = 0.f;
#pragma unroll
        for (int c = 0; c < CDIM; ++c) {
            float t = zs[c * BVEC + tid];
            s = __fadd_rn(s, __fmul_rn(t, t));
        }
        zzs[tid] = s;
    }
    // (covered by the __syncthreads after the first chunk's codebook load)

    const int vbase = (tid >> 4) * 8;   // 16 vector-rows of 8
    const int cbase = (tid & 15) * 8;   // 16 code-cols of 8

    float bd[8];
    int   bi[8];
#pragma unroll
    for (int i = 0; i < 8; ++i) { bd[i] = CUDART_INF_F; bi[i] = 0; }

    for (int chunk = 0; chunk < NCHUNK; ++chunk) {
        // --- load codebook chunk transposed: es[c][code] ---
        {
            int cl = tid >> 1;          // local code 0..127
            int h  = tid & 1;           // half of the 64 dims
            const float4* src = (const float4*)(cb + ((size_t)(chunk * BCODE + cl)) * CDIM + h * 32);
#pragma unroll
            for (int i = 0; i < 8; ++i) {
                float4 v4 = src[i];
                int c = h * 32 + i * 4;
                es[(c + 0) * EPITCH + cl] = v4.x;
                es[(c + 1) * EPITCH + cl] = v4.y;
                es[(c + 2) * EPITCH + cl] = v4.z;
                es[(c + 3) * EPITCH + cl] = v4.w;
            }
        }
        __syncthreads();

        float acc[8][8];
#pragma unroll
        for (int i = 0; i < 8; ++i)
#pragma unroll
            for (int j = 0; j < 8; ++j) acc[i][j] = 0.f;

#pragma unroll 4
        for (int kk = 0; kk < CDIM; ++kk) {
            float4 z0 = *(const float4*)&zs[kk * BVEC + vbase];
            float4 z1 = *(const float4*)&zs[kk * BVEC + vbase + 4];
            float4 e0 = *(const float4*)&es[kk * EPITCH + cbase];
            float4 e1 = *(const float4*)&es[kk * EPITCH + cbase + 4];
            float zr[8] = {z0.x, z0.y, z0.z, z0.w, z1.x, z1.y, z1.z, z1.w};
            float er[8] = {e0.x, e0.y, e0.z, e0.w, e1.x, e1.y, e1.z, e1.w};
#pragma unroll
            for (int i = 0; i < 8; ++i)
#pragma unroll
                for (int j = 0; j < 8; ++j)
                    acc[i][j] = fmaf(zr[i], er[j], acc[i][j]);
        }

        // --- dist = (zz + ee) - 2*dot, running argmin (ascending code order) ---
#pragma unroll
        for (int j = 0; j < 8; ++j) {
            int cg = chunk * BCODE + cbase + j;
            float eev = __ldg(&g_ee[cg]);
#pragma unroll
            for (int i = 0; i < 8; ++i) {
                float s = __fadd_rn(zzs[vbase + i], eev);
                float d = fmaf(-2.0f, acc[i][j], s);
                if (d < bd[i]) { bd[i] = d; bi[i] = cg; }
            }
        }
        __syncthreads();   // before es is overwritten (or reused for reduction)
    }

    // --- cross-thread argmin reduction (16 code-col threads per vector) ---
    {
        int tx = tid & 15;
#pragma unroll
        for (int i = 0; i < 8; ++i) {
            rd[tx * BVEC + vbase + i] = bd[i];
            ri[tx * BVEC + vbase + i] = bi[i];
        }
    }
    __syncthreads();

    if (tid < BVEC) {
        int v = tid;
        float best = rd[v];
        int   bidx = ri[v];
#pragma unroll
        for (int tx = 1; tx < 16; ++tx) {
            float d = rd[tx * BVEC + v];
            int   x = ri[tx * BVEC + v];
            if (d < best || (d == best && x < bidx)) { best = d; bidx = x; }
        }

        // codes output (as float), histogram
        out[Z_ELEMS + (size_t)b * KTOT + k0 + v] = (float)bidx;
        atomicAdd(&g_hist[bidx], 1);

        // gather z_q, write z_q_st = z_e + (z_q - z_e), accumulate loss
        const float4* crow = (const float4*)(cb + (size_t)bidx * CDIM);
        float* obase = out + ((size_t)b * CDIM) * KTOT + k0 + v;
        double lsum = 0.0;
#pragma unroll
        for (int c4 = 0; c4 < CDIM / 4; ++c4) {
            float4 q = __ldg(&crow[c4]);
            float zq[4] = {q.x, q.y, q.z, q.w};
#pragma unroll
            for (int jj = 0; jj < 4; ++jj) {
                int c = c4 * 4 + jj;
                float ze = zs[c * BVEC + v];
                float t  = __fsub_rn(zq[jj], ze);          // (z_q - z_e), fp32
                obase[(size_t)c * KTOT] = __fadd_rn(ze, t); // z_e + (...)
                float t2 = __fmul_rn(t, t);
                lsum += (double)t2;
            }
        }
        // warp reduce (warps 0..3 fully active for tid<128)
#pragma unroll
        for (int o = 16; o > 0; o >>= 1)
            lsum += __shfl_down_sync(0xffffffffu, lsum, o);
        if ((tid & 31) == 0) atomicAdd(&g_loss, lsum);
    }
}

// ---------------------------------------------------------------------------
// finalize: loss_vq + perplexity
// ---------------------------------------------------------------------------
__global__ void vq_finalize(float* __restrict__ out) {
    __shared__ float sred[256];
    int tid = threadIdx.x;
    float ent = 0.f;
    for (int j = tid; j < NCODES; j += 256) {
        float p = (float)g_hist[j] * (1.0f / (float)N_VEC);
        ent += p * logf(p + 1e-10f);
    }
    sred[tid] = ent;
    __syncthreads();
    for (int s = 128; s > 0; s >>= 1) {
        if (tid < s) sred[tid] += sred[tid + s];
        __syncthreads();
    }
    if (tid == 0) {
        // loss_vq = (1 + BETA) * mean((z_q - z_e)^2), BETA = 0.25
        out[Z_ELEMS + N_VEC]     = (float)(g_loss * (1.25 / (double)Z_ELEMS));
        out[Z_ELEMS + N_VEC + 1] = expf(-sred[0]);
    }
}

// ---------------------------------------------------------------------------
extern "C" void kernel_launch(void* const* d_in, const int* in_sizes, int n_in,
                              void* d_out, int out_size) {
    const float* z_e = (const float*)d_in[0];
    const float* cb  = (const float*)d_in[1];
    float* out = (float*)d_out;

    cudaFuncSetAttribute(vq_main, cudaFuncAttributeMaxDynamicSharedMemorySize,
                         SMEM_BYTES);

    vq_prep<<<(NCODES + 255) / 256, 256>>>(cb);
    vq_main<<<dim3(KTOT / BVEC, BATCH), 256, SMEM_BYTES>>>(z_e, cb, out);
    vq_finalize<<<1, 256>>>(out);
}

// round 2
// speedup vs baseline: 1.1051x; 1.1051x over previous
#include <cuda_runtime.h>
#include <math_constants.h>
#include <math.h>

#define CDIM     64
#define NCODES   1024
#define KTOT     2048
#define BATCH    32
#define N_VEC    (BATCH * KTOT)          // 65536
#define Z_ELEMS  (BATCH * CDIM * KTOT)   // 4194304
#define BVEC     64                      // vectors per block
#define BCODE    128                     // codes per chunk
#define NCHUNK   (NCODES / BCODE)        // 8
#define EPITCH   132                     // padded code pitch in smem
#define NTHREADS 128

// smem (floats): zs[64*64] | zzs[64] | ees[128] | es[64*132]
#define ZS_F      (CDIM * BVEC)              // 4096
#define OFF_ZZS   (ZS_F)                     // 4096
#define OFF_EES   (ZS_F + BVEC)              // 4160
#define OFF_ES    (ZS_F + BVEC + BCODE)      // 4288  (x4 = 17152 B, 16B aligned)
#define ES_F      (CDIM * EPITCH)            // 8448
#define SMEM_F    (OFF_ES + ES_F)            // 12736
#define SMEM_BYTES (SMEM_F * 4)              // 50944

__device__ double g_loss_part[1024];   // overwritten every run: no zero-init needed

// ---------------------------------------------------------------------------
// main: distances (f32x2-packed FMA) + argmin + gather + outputs
// grid = (KTOT/BVEC, BATCH) = (32, 32) = 1024 blocks, 128 threads
// ---------------------------------------------------------------------------
__global__ __launch_bounds__(NTHREADS, 3)
void vq_main(const float* __restrict__ z_e, const float* __restrict__ cb,
             float* __restrict__ out) {
    extern __shared__ float sm[];
    float* zs  = sm;                 // [c][v]  64 x 64
    float* zzs = sm + OFF_ZZS;       // [v]
    float* ees = sm + OFF_EES;       // [code]  per-chunk code norms
    float* es  = sm + OFF_ES;        // [c][code] pitch 132
    // post-mainloop reuse of es:
    float* rd  = es;                 // [16][64]
    int*   ri  = (int*)(es + 16 * BVEC);
    float* stq = es + 32 * BVEC;     // staging for z_q_st, 4096 floats

    const int tid = threadIdx.x;
    const int b   = blockIdx.y;
    const int k0  = blockIdx.x * BVEC;

    // --- load z tile: zs[c][v] = z_e[b][c][k0+v]  (float4, coalesced) ---
    const float* zbase = z_e + ((size_t)b * CDIM) * KTOT + k0;
#pragma unroll
    for (int i = 0; i < 8; ++i) {
        int idx4 = tid + i * NTHREADS;       // 0..1023
        int c = idx4 >> 4, v4 = idx4 & 15;
        *(float4*)&zs[c * BVEC + v4 * 4] =
            *(const float4*)(zbase + (size_t)c * KTOT + v4 * 4);
    }
    __syncthreads();

    // --- per-vector squared norm (sequential ascending c, reference order) ---
    if (tid < BVEC) {
        float s = 0.f;
#pragma unroll
        for (int c = 0; c < CDIM; ++c) {
            float t = zs[c * BVEC + tid];
            s = __fadd_rn(s, __fmul_rn(t, t));
        }
        zzs[tid] = s;
    }

    const int vbase = (tid >> 4) * 8;   // 8 vector-rows of 8
    const int cbase = (tid & 15) * 8;   // 16 code-cols of 8

    float bd[8];
    int   bi[8];
    float zzr[8];
#pragma unroll
    for (int i = 0; i < 8; ++i) { bd[i] = CUDART_INF_F; bi[i] = 0; }

    for (int chunk = 0; chunk < NCHUNK; ++chunk) {
        // --- load codebook chunk transposed into es, fuse code-norm compute ---
        {
            const float4* src =
                (const float4*)(cb + ((size_t)(chunk * BCODE + tid)) * CDIM);
            float s = 0.f;
#pragma unroll
            for (int i = 0; i < 16; ++i) {
                float4 v4 = __ldg(&src[i]);
                int c = i * 4;
                es[(c + 0) * EPITCH + tid] = v4.x;
                es[(c + 1) * EPITCH + tid] = v4.y;
                es[(c + 2) * EPITCH + tid] = v4.z;
                es[(c + 3) * EPITCH + tid] = v4.w;
                s = __fadd_rn(s, __fmul_rn(v4.x, v4.x));
                s = __fadd_rn(s, __fmul_rn(v4.y, v4.y));
                s = __fadd_rn(s, __fmul_rn(v4.z, v4.z));
                s = __fadd_rn(s, __fmul_rn(v4.w, v4.w));
            }
            ees[tid] = s;
        }
        __syncthreads();

        if (chunk == 0) {
#pragma unroll
            for (int i = 0; i < 8; ++i) zzr[i] = zzs[vbase + i];
        }

        // --- packed f32x2 outer-product mainloop ---
        unsigned long long acc[8][4];
#pragma unroll
        for (int i = 0; i < 8; ++i)
#pragma unroll
            for (int j = 0; j < 4; ++j) acc[i][j] = 0ull;

#pragma unroll 4
        for (int kk = 0; kk < CDIM; ++kk) {
            float4 z0 = *(const float4*)&zs[kk * BVEC + vbase];
            float4 z1 = *(const float4*)&zs[kk * BVEC + vbase + 4];
            ulonglong2 e0 = *(const ulonglong2*)&es[kk * EPITCH + cbase];
            ulonglong2 e1 = *(const ulonglong2*)&es[kk * EPITCH + cbase + 4];
            float zr[8] = {z0.x, z0.y, z0.z, z0.w, z1.x, z1.y, z1.z, z1.w};
            unsigned long long eb[4] = {e0.x, e0.y, e1.x, e1.y};
            unsigned long long ez[8];
#pragma unroll
            for (int i = 0; i < 8; ++i)
                asm("mov.b64 %0, {%1, %1};" : "=l"(ez[i]) : "f"(zr[i]));
#pragma unroll
            for (int i = 0; i < 8; ++i)
#pragma unroll
                for (int j = 0; j < 4; ++j)
                    asm("fma.rn.f32x2 %0, %1, %2, %0;"
                        : "+l"(acc[i][j]) : "l"(ez[i]), "l"(eb[j]));
        }
        __syncthreads();

        // --- dist = (zz + ee) - 2*dot, running argmin (ascending code order) ---
#pragma unroll
        for (int j = 0; j < 8; ++j) {
            int cg = chunk * BCODE + cbase + j;
            float eev = ees[cbase + j];
#pragma unroll
            for (int i = 0; i < 8; ++i) {
                unsigned long long a = acc[i][j >> 1];
                float dotv = (j & 1) ? __uint_as_float((unsigned)(a >> 32))
                                     : __uint_as_float((unsigned)a);
                float s = __fadd_rn(zzr[i], eev);
                float d = fmaf(-2.0f, dotv, s);
                if (d < bd[i]) { bd[i] = d; bi[i] = cg; }
            }
        }
        // next chunk's es/ees writes are ordered by the sync at loop top
    }
    __syncthreads();   // protect es before reuse as rd/ri

    // --- cross-thread argmin reduction (16 code-col threads per vector) ---
    {
        int tx = tid & 15;
#pragma unroll
        for (int i = 0; i < 8; ++i) {
            rd[tx * BVEC + vbase + i] = bd[i];
            ri[tx * BVEC + vbase + i] = bi[i];
        }
    }
    __syncthreads();

    double* sls = (double*)(sm + OFF_ZZS);   // 2 doubles, zzs dead now

    if (tid < BVEC) {
        int v = tid;
        float best = rd[v];
        int   bidx = ri[v];
#pragma unroll
        for (int tx = 1; tx < 16; ++tx) {
            float d = rd[tx * BVEC + v];
            int   x = ri[tx * BVEC + v];
            if (d < best || (d == best && x < bidx)) { best = d; bidx = x; }
        }

        // codes output (as float)
        out[Z_ELEMS + (size_t)b * KTOT + k0 + v] = (float)bidx;

        // gather z_q, stage z_q_st = z_e + (z_q - z_e), accumulate loss
        const float4* crow = (const float4*)(cb + (size_t)bidx * CDIM);
        double lsum = 0.0;
#pragma unroll
        for (int c4 = 0; c4 < CDIM / 4; ++c4) {
            float4 q = __ldg(&crow[c4]);
            float zq[4] = {q.x, q.y, q.z, q.w};
#pragma unroll
            for (int jj = 0; jj < 4; ++jj) {
                int c = c4 * 4 + jj;
                float ze = zs[c * BVEC + v];
                float t  = __fsub_rn(zq[jj], ze);
                stq[c * BVEC + v] = __fadd_rn(ze, t);
                lsum += (double)__fmul_rn(t, t);
            }
        }
#pragma unroll
        for (int o = 16; o > 0; o >>= 1)
            lsum += __shfl_down_sync(0xffffffffu, lsum, o);
        if ((tid & 31) == 0) sls[tid >> 5] = lsum;
    }
    __syncthreads();

    if (tid == 0)
        g_loss_part[blockIdx.y * gridDim.x + blockIdx.x] = sls[0] + sls[1];

    // --- coalesced z_q_st store ---
    {
        float* ob = out + ((size_t)b * CDIM) * KTOT + k0;
#pragma unroll
        for (int i = 0; i < 8; ++i) {
            int idx4 = tid + i * NTHREADS;
            int c = idx4 >> 4, v4 = idx4 & 15;
            *(float4*)(ob + (size_t)c * KTOT + v4 * 4) =
                *(const float4*)&stq[c * BVEC + v4 * 4];
        }
    }
}

// ---------------------------------------------------------------------------
// finalize: histogram from codes output, perplexity, loss sum
// ---------------------------------------------------------------------------
__global__ void vq_finalize(float* __restrict__ out) {
    __shared__ int    shist[NCODES];
    __shared__ float  sent[NCODES];
    __shared__ double sls[1024];
    int tid = threadIdx.x;
    shist[tid] = 0;
    __syncthreads();

    const float* codes = out + Z_ELEMS;
#pragma unroll
    for (int i = 0; i < N_VEC / 1024; ++i) {
        int c = (int)codes[tid + i * 1024];
        atomicAdd(&shist[c], 1);
    }
    __syncthreads();

    float p = (float)shist[tid] * (1.0f / (float)N_VEC);
    sent[tid] = p * logf(p + 1e-10f);
    sls[tid]  = g_loss_part[tid];
    __syncthreads();

    for (int s = 512; s > 0; s >>= 1) {
        if (tid < s) { sent[tid] += sent[tid + s]; sls[tid] += sls[tid + s]; }
        __syncthreads();
    }
    if (tid == 0) {
        out[Z_ELEMS + N_VEC]     = (float)(sls[0] * (1.25 / (double)Z_ELEMS));
        out[Z_ELEMS + N_VEC + 1] = expf(-sent[0]);
    }
}

// ---------------------------------------------------------------------------
extern "C" void kernel_launch(void* const* d_in, const int* in_sizes, int n_in,
                              void* d_out, int out_size) {
    const float* z_e = (const float*)d_in[0];
    const float* cb  = (const float*)d_in[1];
    float* out = (float*)d_out;

    cudaFuncSetAttribute(vq_main, cudaFuncAttributeMaxDynamicSharedMemorySize,
                         SMEM_BYTES);

    vq_main<<<dim3(KTOT / BVEC, BATCH), NTHREADS, SMEM_BYTES>>>(z_e, cb, out);
    vq_finalize<<<1, 1024>>>(out);
}

// round 6
// speedup vs baseline: 1.2487x; 1.1300x over previous
#include <cuda_runtime.h>
#include <cuda_bf16.h>
#include <math_constants.h>
#include <math.h>

#define CDIM     64
#define NCODES   1024
#define KTOT     2048
#define BATCH    32
#define N_VEC    (BATCH * KTOT)          // 65536
#define Z_ELEMS  (BATCH * CDIM * KTOT)   // 4194304
#define MTILE    128                     // vectors per CTA
#define KSPLIT   192                     // [zh|zh|zl] x [eh|el|eh]
#define NKS      12                      // k16 steps
#define NCHUNKS  8                       // code chunks of 128
#define NTHREADS 256
#define APITCH   200                     // halves per row (192 + 8 pad)
#define BPITCH   200

// smem byte offsets
#define ZS_B     0                        // fp32 z tile [c][v] 64x128 = 32768
#define A_B      32768                    // A halves image 128x200x2 = 51200
#define B_B      83968                    // B halves chunk 128x200x2 = 51200
#define EES_B    135168                   // 128 floats
#define ZZS_B    135680                   // 128 floats
#define RDI_B    136192                   // int2[128]
#define SLS_B    137216                   // 8 doubles
#define SMEM_BYTES 137472

#define B_CHUNK_U4  3200                 // 51200 B / 16

__device__ float  g_ee[NCODES];
__device__ int    g_hist[NCODES];
__device__ double g_loss_part[512];
__device__ __align__(16) unsigned short g_bh[NCODES * BPITCH];   // bf16 split codebook

// ---------------------------------------------------------------------------
__device__ __forceinline__ unsigned smem_u32(const void* p) {
    unsigned a;
    asm("{ .reg .u64 t; cvta.to.shared.u64 t, %1; cvt.u32.u64 %0, t; }"
        : "=r"(a) : "l"(p));
    return a;
}
__device__ __forceinline__ void ldsm4(unsigned& r0, unsigned& r1, unsigned& r2,
                                      unsigned& r3, unsigned addr) {
    asm volatile("ldmatrix.sync.aligned.m8n8.x4.shared.b16 {%0,%1,%2,%3}, [%4];"
                 : "=r"(r0), "=r"(r1), "=r"(r2), "=r"(r3) : "r"(addr));
}
__device__ __forceinline__ void mma16816(float* c, unsigned a0, unsigned a1,
                                         unsigned a2, unsigned a3,
                                         unsigned b0, unsigned b1) {
    asm volatile(
        "mma.sync.aligned.m16n8k16.row.col.f32.bf16.bf16.f32 "
        "{%0,%1,%2,%3}, {%4,%5,%6,%7}, {%8,%9}, {%0,%1,%2,%3};"
        : "+f"(c[0]), "+f"(c[1]), "+f"(c[2]), "+f"(c[3])
        : "r"(a0), "r"(a1), "r"(a2), "r"(a3), "r"(b0), "r"(b1));
}
__device__ __forceinline__ bool better(float da, int ia, float db, int ib) {
    return da < db || (da == db && ia < ib);
}

// ---------------------------------------------------------------------------
// prep: code norms, bf16 split codebook image, zero histogram
// ---------------------------------------------------------------------------
__global__ void vq_prep(const float* __restrict__ cb) {
    int j = blockIdx.x * blockDim.x + threadIdx.x;
    if (j >= NCODES) return;
    const float* row = cb + j * CDIM;
    unsigned short* img = g_bh + j * BPITCH;
    float s = 0.f;
#pragma unroll
    for (int c = 0; c < CDIM; ++c) {
        float e = row[c];
        s = __fadd_rn(s, __fmul_rn(e, e));
        __nv_bfloat16 eh = __float2bfloat16(e);
        __nv_bfloat16 el = __float2bfloat16(e - __bfloat162float(eh));
        img[c]       = __bfloat16_as_ushort(eh);
        img[64 + c]  = __bfloat16_as_ushort(el);
        img[128 + c] = __bfloat16_as_ushort(eh);
    }
#pragma unroll
    for (int c = KSPLIT; c < BPITCH; ++c) img[c] = 0;   // pad deterministic
    g_ee[j]   = s;
    g_hist[j] = 0;
}

// ---------------------------------------------------------------------------
// main: HMMA split-GEMM screen (top-2) + exact fp32 refine + outputs
// grid = 512, block = 256 (8 warps; warp w owns rows 16w..16w+15)
// ---------------------------------------------------------------------------
__global__ __launch_bounds__(NTHREADS, 1)
void vq_main(const float* __restrict__ z_e, const float* __restrict__ cb,
             float* __restrict__ out) {
    extern __shared__ char sm[];
    float*  zs  = (float*)(sm + ZS_B);      // [c][v] 64 x 128
    float*  ees = (float*)(sm + EES_B);
    float*  zzs = (float*)(sm + ZZS_B);
    int2*   rdi = (int2*)(sm + RDI_B);
    double* sls = (double*)(sm + SLS_B);
    const unsigned smem_base = smem_u32(sm);

    const int tid  = threadIdx.x;
    const int w    = tid >> 5;
    const int lane = tid & 31;
    const int b    = blockIdx.x >> 4;
    const int k0v  = (blockIdx.x & 15) * MTILE;

    // --- load z tile (coalesced float4): zs[c][v] = z_e[b][c][k0v+v] ---
    const float* zbase = z_e + ((size_t)b * CDIM) * KTOT + k0v;
#pragma unroll
    for (int i = 0; i < 8; ++i) {
        int idx4 = tid + i * NTHREADS;       // 0..2047
        int c = idx4 >> 5, v4 = idx4 & 31;
        *(float4*)&zs[c * MTILE + v4 * 4] =
            *(const float4*)(zbase + (size_t)c * KTOT + v4 * 4);
    }
    __syncthreads();

    // --- per-vector norm (reference order) + A bf16-split image ---
    if (tid < MTILE) {
        const int m = tid;
        unsigned short* arow = (unsigned short*)(sm + A_B) + m * APITCH;
        float s = 0.f;
#pragma unroll
        for (int c = 0; c < CDIM; ++c) {
            float z = zs[c * MTILE + m];
            s = __fadd_rn(s, __fmul_rn(z, z));
            __nv_bfloat16 zh = __float2bfloat16(z);
            __nv_bfloat16 zl = __float2bfloat16(z - __bfloat162float(zh));
            arow[c]       = __bfloat16_as_ushort(zh);
            arow[64 + c]  = __bfloat16_as_ushort(zh);
            arow[128 + c] = __bfloat16_as_ushort(zl);
        }
        zzs[m] = s;
    }
    __syncthreads();

    // lane-invariant ldmatrix row components
    const int lrow = (lane & 7) + ((lane >> 3) & 1) * 8;   // row within 16
    const int lkof = (lane >> 4) * 8;                      // k half
    const unsigned a_base =
        smem_base + A_B + (unsigned)((w * 16 + lrow) * APITCH + lkof) * 2;

    const float zzr0 = zzs[w * 16 + (lane >> 2)];
    const float zzr1 = zzs[w * 16 + (lane >> 2) + 8];

    float td1[2] = {CUDART_INF_F, CUDART_INF_F};
    float td2[2] = {CUDART_INF_F, CUDART_INF_F};
    int   ti1[2] = {0, 0}, ti2[2] = {0, 0};

    for (int chunk = 0; chunk < NCHUNKS; ++chunk) {
        // --- copy B chunk (flat, coalesced, FULL 3200 uint4) + code norms ---
        {
            const uint4* src = (const uint4*)(g_bh + (size_t)chunk * 128 * BPITCH);
            uint4* dst = (uint4*)(sm + B_B);
#pragma unroll
            for (int i = 0; i < 13; ++i) {
                int idx = tid + i * NTHREADS;
                if (idx < B_CHUNK_U4) dst[idx] = __ldg(&src[idx]);
            }
            if (tid < 128) ees[tid] = g_ee[chunk * 128 + tid];
        }
        __syncthreads();

        for (int ngrp = 0; ngrp < 2; ++ngrp) {
            float acc[8][4];
#pragma unroll
            for (int a = 0; a < 8; ++a)
#pragma unroll
                for (int r = 0; r < 4; ++r) acc[a][r] = 0.f;

            const unsigned b_base = smem_base + B_B +
                (unsigned)((ngrp * 64 + lrow) * BPITCH + lkof) * 2;

#pragma unroll
            for (int s = 0; s < NKS; ++s) {
                unsigned a0, a1, a2, a3;
                ldsm4(a0, a1, a2, a3, a_base + (unsigned)(s * 16) * 2);
#pragma unroll
                for (int g = 0; g < 4; ++g) {
                    unsigned b0, b1, b2, b3;
                    ldsm4(b0, b1, b2, b3,
                          b_base + (unsigned)(g * 16 * BPITCH + s * 16) * 2);
                    mma16816(acc[g * 2 + 0], a0, a1, a2, a3, b0, b2);
                    mma16816(acc[g * 2 + 1], a0, a1, a2, a3, b1, b3);
                }
            }

            // --- screen: d = zz + ee - 2*dot, per-thread top-2 per row ---
#pragma unroll
            for (int a = 0; a < 8; ++a) {
                int e0 = ngrp * 64 + a * 8 + (lane & 3) * 2;
                int cg0 = chunk * 128 + e0;
                float ee0 = ees[e0], ee1 = ees[e0 + 1];
#pragma unroll
                for (int r = 0; r < 4; ++r) {
                    float ee = (r & 1) ? ee1 : ee0;
                    int   cg = cg0 + (r & 1);
                    float zz = (r >> 1) ? zzr1 : zzr0;
                    float d  = fmaf(-2.0f, acc[a][r], zz + ee);
                    int ri = r >> 1;
                    if (d < td1[ri]) {
                        td2[ri] = td1[ri]; ti2[ri] = ti1[ri];
                        td1[ri] = d;       ti1[ri] = cg;
                    } else if (d < td2[ri]) {
                        td2[ri] = d; ti2[ri] = cg;
                    }
                }
            }
        }
        __syncthreads();   // B reused next chunk
    }

    // --- merge top-2 across the quad (lanes differing in bits 0,1) ---
#pragma unroll
    for (int xm = 1; xm <= 2; xm <<= 1) {
#pragma unroll
        for (int ri = 0; ri < 2; ++ri) {
            float e1 = __shfl_xor_sync(0xffffffffu, td1[ri], xm);
            int   j1 = __shfl_xor_sync(0xffffffffu, ti1[ri], xm);
            float e2 = __shfl_xor_sync(0xffffffffu, td2[ri], xm);
            int   j2 = __shfl_xor_sync(0xffffffffu, ti2[ri], xm);
            if (better(e1, j1, td1[ri], ti1[ri])) {
                float n2d; int n2i;
                if (better(td1[ri], ti1[ri], e2, j2)) { n2d = td1[ri]; n2i = ti1[ri]; }
                else                                   { n2d = e2;      n2i = j2; }
                td1[ri] = e1; ti1[ri] = j1; td2[ri] = n2d; ti2[ri] = n2i;
            } else {
                if (better(e1, j1, td2[ri], ti2[ri])) { td2[ri] = e1; ti2[ri] = j1; }
            }
        }
    }
    if ((lane & 3) == 0) {
        rdi[w * 16 + (lane >> 2)]     = make_int2(ti1[0], ti2[0]);
        rdi[w * 16 + (lane >> 2) + 8] = make_int2(ti1[1], ti2[1]);
    }
    __syncthreads();

    // --- exact fp32 refine (R2-identical arithmetic) + outputs ---
    float* stq = (float*)(sm + B_B);   // B dead: 32 KB staging
    if (tid < MTILE) {
        const int m = tid;
        int ci[2] = {rdi[m].x, rdi[m].y};
        float zz = zzs[m];
        float de[2];
#pragma unroll
        for (int t = 0; t < 2; ++t) {
            const float4* crow = (const float4*)(cb + (size_t)ci[t] * CDIM);
            float a = 0.f;
#pragma unroll
            for (int c4 = 0; c4 < CDIM / 4; ++c4) {
                float4 q = __ldg(&crow[c4]);
                a = fmaf(zs[(c4 * 4 + 0) * MTILE + m], q.x, a);
                a = fmaf(zs[(c4 * 4 + 1) * MTILE + m], q.y, a);
                a = fmaf(zs[(c4 * 4 + 2) * MTILE + m], q.z, a);
                a = fmaf(zs[(c4 * 4 + 3) * MTILE + m], q.w, a);
            }
            de[t] = fmaf(-2.0f, a, __fadd_rn(zz, __ldg(&g_ee[ci[t]])));
        }
        int bidx = ci[0];
        if (better(de[1], ci[1], de[0], ci[0])) bidx = ci[1];

        out[Z_ELEMS + (size_t)b * KTOT + k0v + m] = (float)bidx;
        atomicAdd(&g_hist[bidx], 1);

        const float4* crow = (const float4*)(cb + (size_t)bidx * CDIM);
        double lsum = 0.0;
#pragma unroll
        for (int c4 = 0; c4 < CDIM / 4; ++c4) {
            float4 q = __ldg(&crow[c4]);
            float zq[4] = {q.x, q.y, q.z, q.w};
#pragma unroll
            for (int u = 0; u < 4; ++u) {
                int c = c4 * 4 + u;
                float ze = zs[c * MTILE + m];
                float t  = __fsub_rn(zq[u], ze);
                stq[c * MTILE + m] = __fadd_rn(ze, t);
                lsum += (double)__fmul_rn(t, t);
            }
        }
#pragma unroll
        for (int o = 16; o > 0; o >>= 1)
            lsum += __shfl_down_sync(0xffffffffu, lsum, o);
        if ((tid & 31) == 0) sls[tid >> 5] = lsum;
    }
    __syncthreads();
    if (tid == 0)
        g_loss_part[blockIdx.x] = sls[0] + sls[1] + sls[2] + sls[3];

    // --- coalesced z_q_st store ---
    {
        float* ob = out + ((size_t)b * CDIM) * KTOT + k0v;
#pragma unroll
        for (int i = 0; i < 8; ++i) {
            int idx4 = tid + i * NTHREADS;
            int c = idx4 >> 5, v4 = idx4 & 31;
            *(float4*)(ob + (size_t)c * KTOT + v4 * 4) =
                *(const float4*)&stq[c * MTILE + v4 * 4];
        }
    }
}

// ---------------------------------------------------------------------------
// finalize: perplexity from g_hist, loss from partials
// ---------------------------------------------------------------------------
__global__ void vq_finalize(float* __restrict__ out) {
    __shared__ float  sent[1024];
    __shared__ double sls[1024];
    int tid = threadIdx.x;
    float p = (float)g_hist[tid] * (1.0f / (float)N_VEC);
    sent[tid] = p * logf(p + 1e-10f);
    sls[tid]  = (tid < 512) ? g_loss_part[tid] : 0.0;
    __syncthreads();
    for (int s = 512; s > 0; s >>= 1) {
        if (tid < s) { sent[tid] += sent[tid + s]; sls[tid] += sls[tid + s]; }
        __syncthreads();
    }
    if (tid == 0) {
        out[Z_ELEMS + N_VEC]     = (float)(sls[0] * (1.25 / (double)Z_ELEMS));
        out[Z_ELEMS + N_VEC + 1] = expf(-sent[0]);
    }
}

// ---------------------------------------------------------------------------
extern "C" void kernel_launch(void* const* d_in, const int* in_sizes, int n_in,
                              void* d_out, int out_size) {
    const float* z_e = (const float*)d_in[0];
    const float* cb  = (const float*)d_in[1];
    float* out = (float*)d_out;

    cudaFuncSetAttribute(vq_main, cudaFuncAttributeMaxDynamicSharedMemorySize,
                         SMEM_BYTES);

    vq_prep<<<8, 128>>>(cb);
    vq_main<<<512, NTHREADS, SMEM_BYTES>>>(z_e, cb, out);
    vq_finalize<<<1, 1024>>>(out);
}

// round 7
// speedup vs baseline: 1.3614x; 1.0902x over previous
#include <cuda_runtime.h>
#include <cuda_bf16.h>
#include <math_constants.h>
#include <math.h>

#define CDIM     64
#define NCODES   1024
#define KTOT     2048
#define BATCH    32
#define N_VEC    (BATCH * KTOT)          // 65536
#define Z_ELEMS  (BATCH * CDIM * KTOT)   // 4194304
#define MTILE    128                     // vectors per CTA
#define KSPLIT   192                     // [zh|zh|zl] x [eh|el|eh]
#define NKS      12                      // k16 steps
#define NCHUNKS  8                       // code chunks of 128
#define NTHREADS 256
#define APITCH   200                     // halves per row (192 + 8 pad)
#define BPITCH   200

// smem byte offsets
#define ZS_B     0                        // fp32 z tile [c][v] 64x128 = 32768
#define A_B      32768                    // A halves image 128x200x2 = 51200
#define B0_B     83968                    // B chunk buf0 51200
#define B1_B     135168                   // B chunk buf1 51200
#define EES0_B   186368                   // 128 floats
#define EES1_B   186880                   // 128 floats
#define ZZS_B    187392                   // 128 floats
#define RDI_B    187904                   // int2[128]
#define SLS_B    188928                   // 8 doubles
#define SMEM_BYTES 188992

#define B_CHUNK_U4  3200                 // 51200 B / 16

__device__ float  g_ee[NCODES];
__device__ int    g_hist[NCODES];
__device__ double g_loss_part[512];
__device__ __align__(16) unsigned short g_bh[NCODES * BPITCH];   // bf16 split codebook

// ---------------------------------------------------------------------------
__device__ __forceinline__ unsigned smem_u32(const void* p) {
    unsigned a;
    asm("{ .reg .u64 t; cvta.to.shared.u64 t, %1; cvt.u32.u64 %0, t; }"
        : "=r"(a) : "l"(p));
    return a;
}
__device__ __forceinline__ void ldsm4(unsigned& r0, unsigned& r1, unsigned& r2,
                                      unsigned& r3, unsigned addr) {
    asm volatile("ldmatrix.sync.aligned.m8n8.x4.shared.b16 {%0,%1,%2,%3}, [%4];"
                 : "=r"(r0), "=r"(r1), "=r"(r2), "=r"(r3) : "r"(addr));
}
__device__ __forceinline__ void mma16816(float* c, unsigned a0, unsigned a1,
                                         unsigned a2, unsigned a3,
                                         unsigned b0, unsigned b1) {
    asm volatile(
        "mma.sync.aligned.m16n8k16.row.col.f32.bf16.bf16.f32 "
        "{%0,%1,%2,%3}, {%4,%5,%6,%7}, {%8,%9}, {%0,%1,%2,%3};"
        : "+f"(c[0]), "+f"(c[1]), "+f"(c[2]), "+f"(c[3])
        : "r"(a0), "r"(a1), "r"(a2), "r"(a3), "r"(b0), "r"(b1));
}
__device__ __forceinline__ void cpa16(unsigned dst, const void* src) {
    asm volatile("cp.async.cg.shared.global [%0], [%1], 16;"
                 :: "r"(dst), "l"(src));
}
__device__ __forceinline__ void cpa4(unsigned dst, const void* src) {
    asm volatile("cp.async.ca.shared.global [%0], [%1], 4;"
                 :: "r"(dst), "l"(src));
}
__device__ __forceinline__ void cpa_commit() {
    asm volatile("cp.async.commit_group;" ::: "memory");
}
template <int N>
__device__ __forceinline__ void cpa_wait() {
    asm volatile("cp.async.wait_group %0;" :: "n"(N) : "memory");
}
__device__ __forceinline__ bool better(float da, int ia, float db, int ib) {
    return da < db || (da == db && ia < ib);
}

// ---------------------------------------------------------------------------
// prep: code norms (sequential order), bf16 split codebook image, zero hist
// ---------------------------------------------------------------------------
__global__ void vq_prep(const float* __restrict__ cb) {
    int j = blockIdx.x * blockDim.x + threadIdx.x;
    if (j >= NCODES) return;
    const float4* row4 = (const float4*)(cb + j * CDIM);
    float r[CDIM];
#pragma unroll
    for (int q = 0; q < CDIM / 4; ++q) {             // MLP-16 vector loads
        float4 v = __ldg(&row4[q]);
        r[q * 4 + 0] = v.x; r[q * 4 + 1] = v.y;
        r[q * 4 + 2] = v.z; r[q * 4 + 3] = v.w;
    }
    unsigned short* img = g_bh + j * BPITCH;
    float s = 0.f;
#pragma unroll
    for (int c = 0; c < CDIM; ++c) {                 // ascending-c association
        float e = r[c];
        s = __fadd_rn(s, __fmul_rn(e, e));
        __nv_bfloat16 eh = __float2bfloat16(e);
        __nv_bfloat16 el = __float2bfloat16(e - __bfloat162float(eh));
        img[c]       = __bfloat16_as_ushort(eh);
        img[64 + c]  = __bfloat16_as_ushort(el);
        img[128 + c] = __bfloat16_as_ushort(eh);
    }
#pragma unroll
    for (int c = KSPLIT; c < BPITCH; ++c) img[c] = 0;
    g_ee[j]   = s;
    g_hist[j] = 0;
}

// ---------------------------------------------------------------------------
// main: HMMA split-GEMM screen (top-2), cp.async double-buffered B,
//       exact fp32 refine + outputs.  grid = 512, block = 256.
// ---------------------------------------------------------------------------
__global__ __launch_bounds__(NTHREADS, 1)
void vq_main(const float* __restrict__ z_e, const float* __restrict__ cb,
             float* __restrict__ out) {
    extern __shared__ char sm[];
    float*  zs  = (float*)(sm + ZS_B);      // [c][v] 64 x 128
    float*  zzs = (float*)(sm + ZZS_B);
    int2*   rdi = (int2*)(sm + RDI_B);
    double* sls = (double*)(sm + SLS_B);
    const unsigned smem_base = smem_u32(sm);

    const int tid  = threadIdx.x;
    const int w    = tid >> 5;
    const int lane = tid & 31;
    const int b    = blockIdx.x >> 4;
    const int k0v  = (blockIdx.x & 15) * MTILE;

    // --- kick off B chunk 0 prefetch immediately ---
    {
        const uint4* src = (const uint4*)g_bh;
#pragma unroll
        for (int i = 0; i < 13; ++i) {
            int idx = tid + i * NTHREADS;
            if (idx < B_CHUNK_U4) cpa16(smem_base + B0_B + idx * 16, src + idx);
        }
        if (tid < 128) cpa4(smem_base + EES0_B + tid * 4, &g_ee[tid]);
        cpa_commit();
    }

    // --- load z tile (coalesced float4): zs[c][v] = z_e[b][c][k0v+v] ---
    const float* zbase = z_e + ((size_t)b * CDIM) * KTOT + k0v;
#pragma unroll
    for (int i = 0; i < 8; ++i) {
        int idx4 = tid + i * NTHREADS;       // 0..2047
        int c = idx4 >> 5, v4 = idx4 & 31;
        *(float4*)&zs[c * MTILE + v4 * 4] =
            *(const float4*)(zbase + (size_t)c * KTOT + v4 * 4);
    }
    __syncthreads();

    // --- per-vector norm (reference order) + A bf16-split image ---
    if (tid < MTILE) {
        const int m = tid;
        unsigned short* arow = (unsigned short*)(sm + A_B) + m * APITCH;
        float s = 0.f;
#pragma unroll
        for (int c = 0; c < CDIM; ++c) {
            float z = zs[c * MTILE + m];
            s = __fadd_rn(s, __fmul_rn(z, z));
            __nv_bfloat16 zh = __float2bfloat16(z);
            __nv_bfloat16 zl = __float2bfloat16(z - __bfloat162float(zh));
            arow[c]       = __bfloat16_as_ushort(zh);
            arow[64 + c]  = __bfloat16_as_ushort(zh);
            arow[128 + c] = __bfloat16_as_ushort(zl);
        }
        zzs[m] = s;
    }
    __syncthreads();

    // lane-invariant ldmatrix row components
    const int lrow = (lane & 7) + ((lane >> 3) & 1) * 8;   // row within 16
    const int lkof = (lane >> 4) * 8;                      // k half
    const unsigned a_base =
        smem_base + A_B + (unsigned)((w * 16 + lrow) * APITCH + lkof) * 2;

    const float zzr0 = zzs[w * 16 + (lane >> 2)];
    const float zzr1 = zzs[w * 16 + (lane >> 2) + 8];

    float td1[2] = {CUDART_INF_F, CUDART_INF_F};
    float td2[2] = {CUDART_INF_F, CUDART_INF_F};
    int   ti1[2] = {0, 0}, ti2[2] = {0, 0};

    for (int chunk = 0; chunk < NCHUNKS; ++chunk) {
        const int cur = chunk & 1;

        // --- prefetch next chunk into the other buffer ---
        if (chunk < NCHUNKS - 1) {
            const uint4* src =
                (const uint4*)(g_bh + (size_t)(chunk + 1) * 128 * BPITCH);
            unsigned dstb = smem_base + (cur ? B0_B : B1_B);
            unsigned dste = smem_base + (cur ? EES0_B : EES1_B);
#pragma unroll
            for (int i = 0; i < 13; ++i) {
                int idx = tid + i * NTHREADS;
                if (idx < B_CHUNK_U4) cpa16(dstb + idx * 16, src + idx);
            }
            if (tid < 128) cpa4(dste + tid * 4, &g_ee[(chunk + 1) * 128 + tid]);
            cpa_commit();
            cpa_wait<1>();   // current chunk's group complete
        } else {
            cpa_wait<0>();
        }
        __syncthreads();

        const unsigned bbuf = cur ? B1_B : B0_B;
        const float* ees = (const float*)(sm + (cur ? EES1_B : EES0_B));

        for (int ngrp = 0; ngrp < 2; ++ngrp) {
            float acc[8][4];
#pragma unroll
            for (int a = 0; a < 8; ++a)
#pragma unroll
                for (int r = 0; r < 4; ++r) acc[a][r] = 0.f;

            const unsigned b_base = smem_base + bbuf +
                (unsigned)((ngrp * 64 + lrow) * BPITCH + lkof) * 2;

#pragma unroll
            for (int s = 0; s < NKS; ++s) {
                unsigned a0, a1, a2, a3;
                ldsm4(a0, a1, a2, a3, a_base + (unsigned)(s * 16) * 2);
#pragma unroll
                for (int g = 0; g < 4; ++g) {
                    unsigned b0, b1, b2, b3;
                    ldsm4(b0, b1, b2, b3,
                          b_base + (unsigned)(g * 16 * BPITCH + s * 16) * 2);
                    mma16816(acc[g * 2 + 0], a0, a1, a2, a3, b0, b2);
                    mma16816(acc[g * 2 + 1], a0, a1, a2, a3, b1, b3);
                }
            }

            // --- screen: d = zz + ee - 2*dot, per-thread top-2 per row ---
#pragma unroll
            for (int a = 0; a < 8; ++a) {
                int e0 = ngrp * 64 + a * 8 + (lane & 3) * 2;
                int cg0 = chunk * 128 + e0;
                float ee0 = ees[e0], ee1 = ees[e0 + 1];
#pragma unroll
                for (int r = 0; r < 4; ++r) {
                    float ee = (r & 1) ? ee1 : ee0;
                    int   cg = cg0 + (r & 1);
                    float zz = (r >> 1) ? zzr1 : zzr0;
                    float d  = fmaf(-2.0f, acc[a][r], zz + ee);
                    int ri = r >> 1;
                    if (d < td1[ri]) {
                        td2[ri] = td1[ri]; ti2[ri] = ti1[ri];
                        td1[ri] = d;       ti1[ri] = cg;
                    } else if (d < td2[ri]) {
                        td2[ri] = d; ti2[ri] = cg;
                    }
                }
            }
        }
        __syncthreads();   // buffer consumed; next iteration may overwrite it
    }

    // --- merge top-2 across the quad (lanes differing in bits 0,1) ---
#pragma unroll
    for (int xm = 1; xm <= 2; xm <<= 1) {
#pragma unroll
        for (int ri = 0; ri < 2; ++ri) {
            float e1 = __shfl_xor_sync(0xffffffffu, td1[ri], xm);
            int   j1 = __shfl_xor_sync(0xffffffffu, ti1[ri], xm);
            float e2 = __shfl_xor_sync(0xffffffffu, td2[ri], xm);
            int   j2 = __shfl_xor_sync(0xffffffffu, ti2[ri], xm);
            if (better(e1, j1, td1[ri], ti1[ri])) {
                float n2d; int n2i;
                if (better(td1[ri], ti1[ri], e2, j2)) { n2d = td1[ri]; n2i = ti1[ri]; }
                else                                   { n2d = e2;      n2i = j2; }
                td1[ri] = e1; ti1[ri] = j1; td2[ri] = n2d; ti2[ri] = n2i;
            } else {
                if (better(e1, j1, td2[ri], ti2[ri])) { td2[ri] = e1; ti2[ri] = j1; }
            }
        }
    }
    if ((lane & 3) == 0) {
        rdi[w * 16 + (lane >> 2)]     = make_int2(ti1[0], ti2[0]);
        rdi[w * 16 + (lane >> 2) + 8] = make_int2(ti1[1], ti2[1]);
    }
    __syncthreads();

    // --- exact fp32 refine (R2-identical arithmetic) + outputs ---
    float* stq = (float*)(sm + B0_B);   // B dead: 32 KB staging
    if (tid < MTILE) {
        const int m = tid;
        int ci[2] = {rdi[m].x, rdi[m].y};
        float zz = zzs[m];
        float de[2];
#pragma unroll
        for (int t = 0; t < 2; ++t) {
            const float4* crow = (const float4*)(cb + (size_t)ci[t] * CDIM);
            float a = 0.f;
#pragma unroll
            for (int c4 = 0; c4 < CDIM / 4; ++c4) {
                float4 q = __ldg(&crow[c4]);
                a = fmaf(zs[(c4 * 4 + 0) * MTILE + m], q.x, a);
                a = fmaf(zs[(c4 * 4 + 1) * MTILE + m], q.y, a);
                a = fmaf(zs[(c4 * 4 + 2) * MTILE + m], q.z, a);
                a = fmaf(zs[(c4 * 4 + 3) * MTILE + m], q.w, a);
            }
            de[t] = fmaf(-2.0f, a, __fadd_rn(zz, __ldg(&g_ee[ci[t]])));
        }
        int bidx = ci[0];
        if (better(de[1], ci[1], de[0], ci[0])) bidx = ci[1];

        out[Z_ELEMS + (size_t)b * KTOT + k0v + m] = (float)bidx;
        atomicAdd(&g_hist[bidx], 1);

        const float4* crow = (const float4*)(cb + (size_t)bidx * CDIM);
        double lsum = 0.0;
#pragma unroll
        for (int c4 = 0; c4 < CDIM / 4; ++c4) {
            float4 q = __ldg(&crow[c4]);
            float zq[4] = {q.x, q.y, q.z, q.w};
#pragma unroll
            for (int u = 0; u < 4; ++u) {
                int c = c4 * 4 + u;
                float ze = zs[c * MTILE + m];
                float t  = __fsub_rn(zq[u], ze);
                stq[c * MTILE + m] = __fadd_rn(ze, t);
                lsum += (double)__fmul_rn(t, t);
            }
        }
#pragma unroll
        for (int o = 16; o > 0; o >>= 1)
            lsum += __shfl_down_sync(0xffffffffu, lsum, o);
        if ((tid & 31) == 0) sls[tid >> 5] = lsum;
    }
    __syncthreads();
    if (tid == 0)
        g_loss_part[blockIdx.x] = sls[0] + sls[1] + sls[2] + sls[3];

    // --- coalesced z_q_st store ---
    {
        float* ob = out + ((size_t)b * CDIM) * KTOT + k0v;
#pragma unroll
        for (int i = 0; i < 8; ++i) {
            int idx4 = tid + i * NTHREADS;
            int c = idx4 >> 5, v4 = idx4 & 31;
            *(float4*)(ob + (size_t)c * KTOT + v4 * 4) =
                *(const float4*)&stq[c * MTILE + v4 * 4];
        }
    }
}

// ---------------------------------------------------------------------------
// finalize: perplexity from g_hist, loss from partials
// ---------------------------------------------------------------------------
__global__ void vq_finalize(float* __restrict__ out) {
    __shared__ float  sent[1024];
    __shared__ double sls[1024];
    int tid = threadIdx.x;
    float p = (float)g_hist[tid] * (1.0f / (float)N_VEC);
    sent[tid] = p * logf(p + 1e-10f);
    sls[tid]  = (tid < 512) ? g_loss_part[tid] : 0.0;
    __syncthreads();
    for (int s = 512; s > 0; s >>= 1) {
        if (tid < s) { sent[tid] += sent[tid + s]; sls[tid] += sls[tid + s]; }
        __syncthreads();
    }
    if (tid == 0) {
        out[Z_ELEMS + N_VEC]     = (float)(sls[0] * (1.25 / (double)Z_ELEMS));
        out[Z_ELEMS + N_VEC + 1] = expf(-sent[0]);
    }
}

// ---------------------------------------------------------------------------
extern "C" void kernel_launch(void* const* d_in, const int* in_sizes, int n_in,
                              void* d_out, int out_size) {
    const float* z_e = (const float*)d_in[0];
    const float* cb  = (const float*)d_in[1];
    float* out = (float*)d_out;

    cudaFuncSetAttribute(vq_main, cudaFuncAttributeMaxDynamicSharedMemorySize,
                         SMEM_BYTES);

    vq_prep<<<8, 128>>>(cb);
    vq_main<<<512, NTHREADS, SMEM_BYTES>>>(z_e, cb, out);
    vq_finalize<<<1, 1024>>>(out);
}

// round 8
// speedup vs baseline: 1.4038x; 1.0312x over previous
#include <cuda_runtime.h>
#include <cuda_bf16.h>
#include <math_constants.h>
#include <math.h>

#define CDIM     64
#define NCODES   1024
#define KTOT     2048
#define BATCH    32
#define N_VEC    (BATCH * KTOT)          // 65536
#define Z_ELEMS  (BATCH * CDIM * KTOT)   // 4194304
#define MTILE    128                     // vectors per CTA
#define KSPLIT   192                     // [zh|zh|zl] x [eh|el|eh]
#define NKS      12                      // k16 steps
#define NCHUNKS  8                       // code chunks of 128
#define NTHREADS 512
#define APITCH   200                     // halves per row (192 + 8 pad)
#define BPITCH   200

// smem byte offsets
#define ZS_B     0                        // fp32 z tile [c][v] 64x128 = 32768
#define A_B      32768                    // A halves image 128x200x2 = 51200
#define B0_B     83968                    // B chunk buf0 51200
#define B1_B     135168                   // B chunk buf1 51200
#define EES0_B   186368                   // 128 floats
#define EES1_B   186880                   // 128 floats
#define ZZS_B    187392                   // 128 floats
#define RDI_B    187904                   // int2[2][128] = 2048
#define SLS_B    189952                   // 4 doubles
#define SMEM_BYTES 190016

#define B_CHUNK_U4  3200                 // 51200 B / 16

__device__ float  g_ee[NCODES];
__device__ int    g_hist[NCODES];
__device__ double g_loss_part[512];
__device__ __align__(16) unsigned short g_bh[NCODES * BPITCH];   // bf16 split codebook

// ---------------------------------------------------------------------------
__device__ __forceinline__ unsigned smem_u32(const void* p) {
    unsigned a;
    asm("{ .reg .u64 t; cvta.to.shared.u64 t, %1; cvt.u32.u64 %0, t; }"
        : "=r"(a) : "l"(p));
    return a;
}
__device__ __forceinline__ void ldsm4(unsigned& r0, unsigned& r1, unsigned& r2,
                                      unsigned& r3, unsigned addr) {
    asm volatile("ldmatrix.sync.aligned.m8n8.x4.shared.b16 {%0,%1,%2,%3}, [%4];"
                 : "=r"(r0), "=r"(r1), "=r"(r2), "=r"(r3) : "r"(addr));
}
__device__ __forceinline__ void mma16816(float* c, unsigned a0, unsigned a1,
                                         unsigned a2, unsigned a3,
                                         unsigned b0, unsigned b1) {
    asm volatile(
        "mma.sync.aligned.m16n8k16.row.col.f32.bf16.bf16.f32 "
        "{%0,%1,%2,%3}, {%4,%5,%6,%7}, {%8,%9}, {%0,%1,%2,%3};"
        : "+f"(c[0]), "+f"(c[1]), "+f"(c[2]), "+f"(c[3])
        : "r"(a0), "r"(a1), "r"(a2), "r"(a3), "r"(b0), "r"(b1));
}
__device__ __forceinline__ void cpa16(unsigned dst, const void* src) {
    asm volatile("cp.async.cg.shared.global [%0], [%1], 16;"
                 :: "r"(dst), "l"(src));
}
__device__ __forceinline__ void cpa4(unsigned dst, const void* src) {
    asm volatile("cp.async.ca.shared.global [%0], [%1], 4;"
                 :: "r"(dst), "l"(src));
}
__device__ __forceinline__ void cpa_commit() {
    asm volatile("cp.async.commit_group;" ::: "memory");
}
template <int N>
__device__ __forceinline__ void cpa_wait() {
    asm volatile("cp.async.wait_group %0;" :: "n"(N) : "memory");
}
__device__ __forceinline__ bool better(float da, int ia, float db, int ib) {
    return da < db || (da == db && ia < ib);
}

// ---------------------------------------------------------------------------
// prep: code norms (sequential order), bf16 split codebook image, zero hist
// ---------------------------------------------------------------------------
__global__ void vq_prep(const float* __restrict__ cb) {
    int j = blockIdx.x * blockDim.x + threadIdx.x;
    if (j >= NCODES) return;
    const float4* row4 = (const float4*)(cb + j * CDIM);
    float r[CDIM];
#pragma unroll
    for (int q = 0; q < CDIM / 4; ++q) {
        float4 v = __ldg(&row4[q]);
        r[q * 4 + 0] = v.x; r[q * 4 + 1] = v.y;
        r[q * 4 + 2] = v.z; r[q * 4 + 3] = v.w;
    }
    unsigned short* img = g_bh + j * BPITCH;
    float s = 0.f;
#pragma unroll
    for (int c = 0; c < CDIM; ++c) {                 // ascending-c association
        float e = r[c];
        s = __fadd_rn(s, __fmul_rn(e, e));
        __nv_bfloat16 eh = __float2bfloat16(e);
        __nv_bfloat16 el = __float2bfloat16(e - __bfloat162float(eh));
        img[c]       = __bfloat16_as_ushort(eh);
        img[64 + c]  = __bfloat16_as_ushort(el);
        img[128 + c] = __bfloat16_as_ushort(eh);
    }
#pragma unroll
    for (int c = KSPLIT; c < BPITCH; ++c) img[c] = 0;
    g_ee[j]   = s;
    g_hist[j] = 0;
}

// ---------------------------------------------------------------------------
// main: HMMA split-GEMM screen, 16 warps (warp = 16 rows x one N-half),
//       cp.async double-buffered B, exact fp32 refine of 4 candidates.
// grid = 512, block = 512.
// ---------------------------------------------------------------------------
__global__ __launch_bounds__(NTHREADS, 1)
void vq_main(const float* __restrict__ z_e, const float* __restrict__ cb,
             float* __restrict__ out) {
    extern __shared__ char sm[];
    float*  zs  = (float*)(sm + ZS_B);      // [c][v] 64 x 128
    float*  zzs = (float*)(sm + ZZS_B);
    int2*   rdi = (int2*)(sm + RDI_B);      // [ng][row]
    double* sls = (double*)(sm + SLS_B);
    const unsigned smem_base = smem_u32(sm);

    const int tid  = threadIdx.x;
    const int w    = tid >> 5;
    const int lane = tid & 31;
    const int wm   = w & 7;                 // row group
    const int ng   = w >> 3;                // N half
    const int b    = blockIdx.x >> 4;
    const int k0v  = (blockIdx.x & 15) * MTILE;

    // --- kick off B chunk 0 prefetch immediately ---
    {
        const uint4* src = (const uint4*)g_bh;
#pragma unroll
        for (int i = 0; i < 7; ++i) {
            int idx = tid + i * NTHREADS;
            if (idx < B_CHUNK_U4) cpa16(smem_base + B0_B + idx * 16, src + idx);
        }
        if (tid < 128) cpa4(smem_base + EES0_B + tid * 4, &g_ee[tid]);
        cpa_commit();
    }

    // --- load z tile (coalesced float4): zs[c][v] = z_e[b][c][k0v+v] ---
    const float* zbase = z_e + ((size_t)b * CDIM) * KTOT + k0v;
#pragma unroll
    for (int i = 0; i < 4; ++i) {
        int idx4 = tid + i * NTHREADS;       // 0..2047
        int c = idx4 >> 5, v4 = idx4 & 31;
        *(float4*)&zs[c * MTILE + v4 * 4] =
            *(const float4*)(zbase + (size_t)c * KTOT + v4 * 4);
    }
    __syncthreads();

    // --- per-vector norm (reference order) + A bf16-split image ---
    if (tid < MTILE) {
        const int m = tid;
        unsigned short* arow = (unsigned short*)(sm + A_B) + m * APITCH;
        float s = 0.f;
#pragma unroll
        for (int c = 0; c < CDIM; ++c) {
            float z = zs[c * MTILE + m];
            s = __fadd_rn(s, __fmul_rn(z, z));
            __nv_bfloat16 zh = __float2bfloat16(z);
            __nv_bfloat16 zl = __float2bfloat16(z - __bfloat162float(zh));
            arow[c]       = __bfloat16_as_ushort(zh);
            arow[64 + c]  = __bfloat16_as_ushort(zh);
            arow[128 + c] = __bfloat16_as_ushort(zl);
        }
        zzs[m] = s;
    }
    __syncthreads();

    // lane-invariant ldmatrix row components
    const int lrow = (lane & 7) + ((lane >> 3) & 1) * 8;   // row within 16
    const int lkof = (lane >> 4) * 8;                      // k half
    const unsigned a_base =
        smem_base + A_B + (unsigned)((wm * 16 + lrow) * APITCH + lkof) * 2;

    const float zzr0 = zzs[wm * 16 + (lane >> 2)];
    const float zzr1 = zzs[wm * 16 + (lane >> 2) + 8];

    float td1[2] = {CUDART_INF_F, CUDART_INF_F};
    float td2[2] = {CUDART_INF_F, CUDART_INF_F};
    int   ti1[2] = {0, 0}, ti2[2] = {0, 0};

    for (int chunk = 0; chunk < NCHUNKS; ++chunk) {
        const int cur = chunk & 1;

        // --- prefetch next chunk into the other buffer ---
        if (chunk < NCHUNKS - 1) {
            const uint4* src =
                (const uint4*)(g_bh + (size_t)(chunk + 1) * 128 * BPITCH);
            unsigned dstb = smem_base + (cur ? B0_B : B1_B);
            unsigned dste = smem_base + (cur ? EES0_B : EES1_B);
#pragma unroll
            for (int i = 0; i < 7; ++i) {
                int idx = tid + i * NTHREADS;
                if (idx < B_CHUNK_U4) cpa16(dstb + idx * 16, src + idx);
            }
            if (tid < 128) cpa4(dste + tid * 4, &g_ee[(chunk + 1) * 128 + tid]);
            cpa_commit();
            cpa_wait<1>();   // current chunk's group complete
        } else {
            cpa_wait<0>();
        }
        __syncthreads();

        const unsigned bbuf = cur ? B1_B : B0_B;
        const float* ees = (const float*)(sm + (cur ? EES1_B : EES0_B));

        float acc[8][4];
#pragma unroll
        for (int a = 0; a < 8; ++a)
#pragma unroll
            for (int r = 0; r < 4; ++r) acc[a][r] = 0.f;

        const unsigned b_base = smem_base + bbuf +
            (unsigned)((ng * 64 + lrow) * BPITCH + lkof) * 2;

#pragma unroll
        for (int s = 0; s < NKS; ++s) {
            unsigned a0, a1, a2, a3;
            ldsm4(a0, a1, a2, a3, a_base + (unsigned)(s * 16) * 2);
#pragma unroll
            for (int g = 0; g < 4; ++g) {
                unsigned b0, b1, b2, b3;
                ldsm4(b0, b1, b2, b3,
                      b_base + (unsigned)(g * 16 * BPITCH + s * 16) * 2);
                mma16816(acc[g * 2 + 0], a0, a1, a2, a3, b0, b2);
                mma16816(acc[g * 2 + 1], a0, a1, a2, a3, b1, b3);
            }
        }

        // --- screen: d = zz + ee - 2*dot, per-thread top-2 per row ---
#pragma unroll
        for (int a = 0; a < 8; ++a) {
            int e0 = ng * 64 + a * 8 + (lane & 3) * 2;
            int cg0 = chunk * 128 + e0;
            float ee0 = ees[e0], ee1 = ees[e0 + 1];
#pragma unroll
            for (int r = 0; r < 4; ++r) {
                float ee = (r & 1) ? ee1 : ee0;
                int   cg = cg0 + (r & 1);
                float zz = (r >> 1) ? zzr1 : zzr0;
                float d  = fmaf(-2.0f, acc[a][r], zz + ee);
                int ri = r >> 1;
                if (d < td1[ri]) {
                    td2[ri] = td1[ri]; ti2[ri] = ti1[ri];
                    td1[ri] = d;       ti1[ri] = cg;
                } else if (d < td2[ri]) {
                    td2[ri] = d; ti2[ri] = cg;
                }
            }
        }
        __syncthreads();   // buffer consumed; next iteration may overwrite it
    }

    // --- merge top-2 across the quad (lanes differing in bits 0,1) ---
#pragma unroll
    for (int xm = 1; xm <= 2; xm <<= 1) {
#pragma unroll
        for (int ri = 0; ri < 2; ++ri) {
            float e1 = __shfl_xor_sync(0xffffffffu, td1[ri], xm);
            int   j1 = __shfl_xor_sync(0xffffffffu, ti1[ri], xm);
            float e2 = __shfl_xor_sync(0xffffffffu, td2[ri], xm);
            int   j2 = __shfl_xor_sync(0xffffffffu, ti2[ri], xm);
            if (better(e1, j1, td1[ri], ti1[ri])) {
                float n2d; int n2i;
                if (better(td1[ri], ti1[ri], e2, j2)) { n2d = td1[ri]; n2i = ti1[ri]; }
                else                                   { n2d = e2;      n2i = j2; }
                td1[ri] = e1; ti1[ri] = j1; td2[ri] = n2d; ti2[ri] = n2i;
            } else {
                if (better(e1, j1, td2[ri], ti2[ri])) { td2[ri] = e1; ti2[ri] = j1; }
            }
        }
    }
    if ((lane & 3) == 0) {
        rdi[ng * MTILE + wm * 16 + (lane >> 2)]     = make_int2(ti1[0], ti2[0]);
        rdi[ng * MTILE + wm * 16 + (lane >> 2) + 8] = make_int2(ti1[1], ti2[1]);
    }
    __syncthreads();

    // --- exact fp32 refine of 4 candidates (R2-identical arithmetic) ---
    float* stq = (float*)(sm + B0_B);   // B dead: 32 KB staging
    if (tid < MTILE) {
        const int m = tid;
        int ci[4] = {rdi[m].x, rdi[m].y, rdi[MTILE + m].x, rdi[MTILE + m].y};
        float zz = zzs[m];
        int bidx = -1;
        float bde = CUDART_INF_F;
#pragma unroll
        for (int t = 0; t < 4; ++t) {
            const float4* crow = (const float4*)(cb + (size_t)ci[t] * CDIM);
            float a = 0.f;
#pragma unroll
            for (int c4 = 0; c4 < CDIM / 4; ++c4) {
                float4 q = __ldg(&crow[c4]);
                a = fmaf(zs[(c4 * 4 + 0) * MTILE + m], q.x, a);
                a = fmaf(zs[(c4 * 4 + 1) * MTILE + m], q.y, a);
                a = fmaf(zs[(c4 * 4 + 2) * MTILE + m], q.z, a);
                a = fmaf(zs[(c4 * 4 + 3) * MTILE + m], q.w, a);
            }
            float de = fmaf(-2.0f, a, __fadd_rn(zz, __ldg(&g_ee[ci[t]])));
            if (bidx < 0 || better(de, ci[t], bde, bidx)) { bde = de; bidx = ci[t]; }
        }

        out[Z_ELEMS + (size_t)b * KTOT + k0v + m] = (float)bidx;
        atomicAdd(&g_hist[bidx], 1);

        const float4* crow = (const float4*)(cb + (size_t)bidx * CDIM);
        double lsum = 0.0;
#pragma unroll
        for (int c4 = 0; c4 < CDIM / 4; ++c4) {
            float4 q = __ldg(&crow[c4]);
            float zq[4] = {q.x, q.y, q.z, q.w};
#pragma unroll
            for (int u = 0; u < 4; ++u) {
                int c = c4 * 4 + u;
                float ze = zs[c * MTILE + m];
                float t  = __fsub_rn(zq[u], ze);
                stq[c * MTILE + m] = __fadd_rn(ze, t);
                lsum += (double)__fmul_rn(t, t);
            }
        }
#pragma unroll
        for (int o = 16; o > 0; o >>= 1)
            lsum += __shfl_down_sync(0xffffffffu, lsum, o);
        if ((tid & 31) == 0) sls[tid >> 5] = lsum;
    }
    __syncthreads();
    if (tid == 0)
        g_loss_part[blockIdx.x] = sls[0] + sls[1] + sls[2] + sls[3];

    // --- coalesced z_q_st store ---
    {
        float* ob = out + ((size_t)b * CDIM) * KTOT + k0v;
#pragma unroll
        for (int i = 0; i < 4; ++i) {
            int idx4 = tid + i * NTHREADS;
            int c = idx4 >> 5, v4 = idx4 & 31;
            *(float4*)(ob + (size_t)c * KTOT + v4 * 4) =
                *(const float4*)&stq[c * MTILE + v4 * 4];
        }
    }
}

// ---------------------------------------------------------------------------
// finalize: perplexity from g_hist, loss from partials
// ---------------------------------------------------------------------------
__global__ void vq_finalize(float* __restrict__ out) {
    __shared__ float  sent[1024];
    __shared__ double sls[1024];
    int tid = threadIdx.x;
    float p = (float)g_hist[tid] * (1.0f / (float)N_VEC);
    sent[tid] = p * logf(p + 1e-10f);
    sls[tid]  = (tid < 512) ? g_loss_part[tid] : 0.0;
    __syncthreads();
    for (int s = 512; s > 0; s >>= 1) {
        if (tid < s) { sent[tid] += sent[tid + s]; sls[tid] += sls[tid + s]; }
        __syncthreads();
    }
    if (tid == 0) {
        out[Z_ELEMS + N_VEC]     = (float)(sls[0] * (1.25 / (double)Z_ELEMS));
        out[Z_ELEMS + N_VEC + 1] = expf(-sent[0]);
    }
}

// ---------------------------------------------------------------------------
extern "C" void kernel_launch(void* const* d_in, const int* in_sizes, int n_in,
                              void* d_out, int out_size) {
    const float* z_e = (const float*)d_in[0];
    const float* cb  = (const float*)d_in[1];
    float* out = (float*)d_out;

    cudaFuncSetAttribute(vq_main, cudaFuncAttributeMaxDynamicSharedMemorySize,
                         SMEM_BYTES);

    vq_prep<<<8, 128>>>(cb);
    vq_main<<<512, NTHREADS, SMEM_BYTES>>>(z_e, cb, out);
    vq_finalize<<<1, 1024>>>(out);
}

// round 9
// speedup vs baseline: 1.4807x; 1.0548x over previous
#include <cuda_runtime.h>
#include <cuda_bf16.h>
#include <math_constants.h>
#include <math.h>

#define CDIM     64
#define NCODES   1024
#define KTOT     2048
#define BATCH    32
#define N_VEC    (BATCH * KTOT)          // 65536
#define Z_ELEMS  (BATCH * CDIM * KTOT)   // 4194304
#define MTILE    128                     // vectors per CTA
#define KSPLIT   192                     // [zh|zh|zl] x [eh|el|eh]
#define NKS      12                      // k16 steps
#define NCHUNKS  8                       // code chunks of 128
#define NTHREADS 512
#define NGRID    512
#define APITCH   200                     // halves per row (192 + 8 pad)
#define BPITCH   200

// smem byte offsets
#define ZS_B     0                        // fp32 z tile [c][v] 64x128 = 32768
#define A_B      32768                    // A halves image 128x200x2 = 51200
#define B0_B     83968                    // B chunk buf0 51200
#define B1_B     135168                   // B chunk buf1 51200 (reused: merge arrays)
#define EES0_B   186368                   // 128 floats
#define EES1_B   186880                   // 128 floats
#define ZZS_B    187392                   // 128 floats
#define SLS_B    187904                   // 16 doubles
#define FLG_B    188032                   // flag int
#define RED_B    188096                   // finalize reduction: 512 f + 512 d = 6144
#define SMEM_BYTES 194240

#define B_CHUNK_U4  3200                 // 51200 B / 16

__device__ float  g_ee[NCODES];
__device__ int    g_hist[NCODES];
__device__ double g_loss_part[NGRID];
__device__ int    g_count = 0;
__device__ __align__(16) unsigned short g_bh[NCODES * BPITCH];   // bf16 split codebook

// ---------------------------------------------------------------------------
__device__ __forceinline__ unsigned smem_u32(const void* p) {
    unsigned a;
    asm("{ .reg .u64 t; cvta.to.shared.u64 t, %1; cvt.u32.u64 %0, t; }"
        : "=r"(a) : "l"(p));
    return a;
}
__device__ __forceinline__ void ldsm4(unsigned& r0, unsigned& r1, unsigned& r2,
                                      unsigned& r3, unsigned addr) {
    asm volatile("ldmatrix.sync.aligned.m8n8.x4.shared.b16 {%0,%1,%2,%3}, [%4];"
                 : "=r"(r0), "=r"(r1), "=r"(r2), "=r"(r3) : "r"(addr));
}
__device__ __forceinline__ void mma16816(float* c, unsigned a0, unsigned a1,
                                         unsigned a2, unsigned a3,
                                         unsigned b0, unsigned b1) {
    asm volatile(
        "mma.sync.aligned.m16n8k16.row.col.f32.bf16.bf16.f32 "
        "{%0,%1,%2,%3}, {%4,%5,%6,%7}, {%8,%9}, {%0,%1,%2,%3};"
        : "+f"(c[0]), "+f"(c[1]), "+f"(c[2]), "+f"(c[3])
        : "r"(a0), "r"(a1), "r"(a2), "r"(a3), "r"(b0), "r"(b1));
}
__device__ __forceinline__ void cpa16(unsigned dst, const void* src) {
    asm volatile("cp.async.cg.shared.global [%0], [%1], 16;"
                 :: "r"(dst), "l"(src));
}
__device__ __forceinline__ void cpa4(unsigned dst, const void* src) {
    asm volatile("cp.async.ca.shared.global [%0], [%1], 4;"
                 :: "r"(dst), "l"(src));
}
__device__ __forceinline__ void cpa_commit() {
    asm volatile("cp.async.commit_group;" ::: "memory");
}
template <int N>
__device__ __forceinline__ void cpa_wait() {
    asm volatile("cp.async.wait_group %0;" :: "n"(N) : "memory");
}
__device__ __forceinline__ bool better(float da, int ia, float db, int ib) {
    return da < db || (da == db && ia < ib);
}

// ---------------------------------------------------------------------------
// prep: code norms (sequential order), bf16 split codebook image, zero hist
// ---------------------------------------------------------------------------
__global__ void vq_prep(const float* __restrict__ cb) {
    int j = blockIdx.x * blockDim.x + threadIdx.x;
    if (j >= NCODES) return;
    const float4* row4 = (const float4*)(cb + j * CDIM);
    float r[CDIM];
#pragma unroll
    for (int q = 0; q < CDIM / 4; ++q) {
        float4 v = __ldg(&row4[q]);
        r[q * 4 + 0] = v.x; r[q * 4 + 1] = v.y;
        r[q * 4 + 2] = v.z; r[q * 4 + 3] = v.w;
    }
    unsigned short* img = g_bh + j * BPITCH;
    float s = 0.f;
#pragma unroll
    for (int c = 0; c < CDIM; ++c) {                 // ascending-c association
        float e = r[c];
        s = __fadd_rn(s, __fmul_rn(e, e));
        __nv_bfloat16 eh = __float2bfloat16(e);
        __nv_bfloat16 el = __float2bfloat16(e - __bfloat162float(eh));
        img[c]       = __bfloat16_as_ushort(eh);
        img[64 + c]  = __bfloat16_as_ushort(el);
        img[128 + c] = __bfloat16_as_ushort(eh);
    }
#pragma unroll
    for (int c = KSPLIT; c < BPITCH; ++c) img[c] = 0;
    g_ee[j]   = s;
    g_hist[j] = 0;
}

// ---------------------------------------------------------------------------
// main: HMMA screen (warp = 32 rows x 32 codes), double-buffered B,
//       exact fp32 refine, fused finalize (last CTA). grid=512, block=512.
// ---------------------------------------------------------------------------
__global__ __launch_bounds__(NTHREADS, 1)
void vq_main(const float* __restrict__ z_e, const float* __restrict__ cb,
             float* __restrict__ out) {
    extern __shared__ char sm[];
    float*  zs  = (float*)(sm + ZS_B);      // [c][v] 64 x 128
    float*  zzs = (float*)(sm + ZZS_B);
    double* sls = (double*)(sm + SLS_B);
    int*    flg = (int*)(sm + FLG_B);
    const unsigned smem_base = smem_u32(sm);

    const int tid  = threadIdx.x;
    const int w    = tid >> 5;
    const int lane = tid & 31;
    const int rg   = w & 3;                 // row group: rows 32rg..32rg+31
    const int cg   = w >> 2;                // code quarter: codes 32cg..32cg+31
    const int b    = blockIdx.x >> 4;
    const int k0v  = (blockIdx.x & 15) * MTILE;

    // --- kick off B chunk 0 prefetch immediately ---
    {
        const uint4* src = (const uint4*)g_bh;
#pragma unroll
        for (int i = 0; i < 7; ++i) {
            int idx = tid + i * NTHREADS;
            if (idx < B_CHUNK_U4) cpa16(smem_base + B0_B + idx * 16, src + idx);
        }
        if (tid < 128) cpa4(smem_base + EES0_B + tid * 4, &g_ee[tid]);
        cpa_commit();
    }

    // --- load z tile (coalesced float4): zs[c][v] = z_e[b][c][k0v+v] ---
    const float* zbase = z_e + ((size_t)b * CDIM) * KTOT + k0v;
#pragma unroll
    for (int i = 0; i < 4; ++i) {
        int idx4 = tid + i * NTHREADS;       // 0..2047
        int c = idx4 >> 5, v4 = idx4 & 31;
        *(float4*)&zs[c * MTILE + v4 * 4] =
            *(const float4*)(zbase + (size_t)c * KTOT + v4 * 4);
    }
    __syncthreads();

    // --- per-vector norm (reference order) + A bf16-split image ---
    if (tid < MTILE) {
        const int m = tid;
        unsigned short* arow = (unsigned short*)(sm + A_B) + m * APITCH;
        float s = 0.f;
#pragma unroll
        for (int c = 0; c < CDIM; ++c) {
            float z = zs[c * MTILE + m];
            s = __fadd_rn(s, __fmul_rn(z, z));
            __nv_bfloat16 zh = __float2bfloat16(z);
            __nv_bfloat16 zl = __float2bfloat16(z - __bfloat162float(zh));
            arow[c]       = __bfloat16_as_ushort(zh);
            arow[64 + c]  = __bfloat16_as_ushort(zh);
            arow[128 + c] = __bfloat16_as_ushort(zl);
        }
        zzs[m] = s;
    }
    __syncthreads();

    // lane-invariant ldmatrix row components
    const int lrow = (lane & 7) + ((lane >> 3) & 1) * 8;   // row within 16
    const int lkof = (lane >> 4) * 8;                      // k half
    const unsigned a_base =
        smem_base + A_B + (unsigned)((rg * 32 + lrow) * APITCH + lkof) * 2;

    // this thread's 4 row norms: rows rg*32 + {0,8,16,24} + lane/4
    float zzr[4];
#pragma unroll
    for (int ri = 0; ri < 4; ++ri)
        zzr[ri] = zzs[rg * 32 + ((ri >> 1) * 16) + ((ri & 1) * 8) + (lane >> 2)];

    float td1[4], td2[4];
    int   ti1[4], ti2[4];
#pragma unroll
    for (int ri = 0; ri < 4; ++ri) {
        td1[ri] = CUDART_INF_F; td2[ri] = CUDART_INF_F;
        ti1[ri] = 0; ti2[ri] = 0;
    }

    for (int chunk = 0; chunk < NCHUNKS; ++chunk) {
        const int cur = chunk & 1;

        if (chunk < NCHUNKS - 1) {
            const uint4* src =
                (const uint4*)(g_bh + (size_t)(chunk + 1) * 128 * BPITCH);
            unsigned dstb = smem_base + (cur ? B0_B : B1_B);
            unsigned dste = smem_base + (cur ? EES0_B : EES1_B);
#pragma unroll
            for (int i = 0; i < 7; ++i) {
                int idx = tid + i * NTHREADS;
                if (idx < B_CHUNK_U4) cpa16(dstb + idx * 16, src + idx);
            }
            if (tid < 128) cpa4(dste + tid * 4, &g_ee[(chunk + 1) * 128 + tid]);
            cpa_commit();
            cpa_wait<1>();
        } else {
            cpa_wait<0>();
        }
        __syncthreads();

        const unsigned bbuf = cur ? B1_B : B0_B;
        const float* ees = (const float*)(sm + (cur ? EES1_B : EES0_B));

        float acc[2][4][4];
#pragma unroll
        for (int rf = 0; rf < 2; ++rf)
#pragma unroll
            for (int j = 0; j < 4; ++j)
#pragma unroll
                for (int r = 0; r < 4; ++r) acc[rf][j][r] = 0.f;

        const unsigned b_base = smem_base + bbuf +
            (unsigned)((cg * 32 + lrow) * BPITCH + lkof) * 2;

#pragma unroll
        for (int s = 0; s < NKS; ++s) {
            unsigned a0, a1, a2, a3, e0, e1, e2, e3;
            ldsm4(a0, a1, a2, a3, a_base + (unsigned)(s * 16) * 2);
            ldsm4(e0, e1, e2, e3,
                  a_base + (unsigned)(16 * APITCH + s * 16) * 2);
            unsigned b0, b1, b2, b3, c0, c1, c2, c3;
            ldsm4(b0, b1, b2, b3, b_base + (unsigned)(s * 16) * 2);
            ldsm4(c0, c1, c2, c3,
                  b_base + (unsigned)(16 * BPITCH + s * 16) * 2);
            // rf 0: rows rg*32+0..15 ; rf 1: rows +16..31
            mma16816(acc[0][0], a0, a1, a2, a3, b0, b2);
            mma16816(acc[0][1], a0, a1, a2, a3, b1, b3);
            mma16816(acc[0][2], a0, a1, a2, a3, c0, c2);
            mma16816(acc[0][3], a0, a1, a2, a3, c1, c3);
            mma16816(acc[1][0], e0, e1, e2, e3, b0, b2);
            mma16816(acc[1][1], e0, e1, e2, e3, b1, b3);
            mma16816(acc[1][2], e0, e1, e2, e3, c0, c2);
            mma16816(acc[1][3], e0, e1, e2, e3, c1, c3);
        }

        // --- screen: d = zz + ee - 2*dot, per-thread top-2 per row ---
#pragma unroll
        for (int rf = 0; rf < 2; ++rf) {
#pragma unroll
            for (int j = 0; j < 4; ++j) {
                int e0i = cg * 32 + j * 8 + (lane & 3) * 2;
                int cg0 = chunk * 128 + e0i;
                float ee0 = ees[e0i], ee1 = ees[e0i + 1];
#pragma unroll
                for (int r = 0; r < 4; ++r) {
                    float ee = (r & 1) ? ee1 : ee0;
                    int   cgi = cg0 + (r & 1);
                    int   ri = rf * 2 + (r >> 1);
                    float d  = fmaf(-2.0f, acc[rf][j][r], zzr[ri] + ee);
                    if (d < td1[ri]) {
                        td2[ri] = td1[ri]; ti2[ri] = ti1[ri];
                        td1[ri] = d;       ti1[ri] = cgi;
                    } else if (d < td2[ri]) {
                        td2[ri] = d; ti2[ri] = cgi;
                    }
                }
            }
        }
        __syncthreads();
    }

    // --- merge top-2 across the quad (lanes differing in bits 0,1) ---
#pragma unroll
    for (int xm = 1; xm <= 2; xm <<= 1) {
#pragma unroll
        for (int ri = 0; ri < 4; ++ri) {
            float e1 = __shfl_xor_sync(0xffffffffu, td1[ri], xm);
            int   j1 = __shfl_xor_sync(0xffffffffu, ti1[ri], xm);
            float e2 = __shfl_xor_sync(0xffffffffu, td2[ri], xm);
            int   j2 = __shfl_xor_sync(0xffffffffu, ti2[ri], xm);
            if (better(e1, j1, td1[ri], ti1[ri])) {
                float n2d; int n2i;
                if (better(td1[ri], ti1[ri], e2, j2)) { n2d = td1[ri]; n2i = ti1[ri]; }
                else                                   { n2d = e2;      n2i = j2; }
                td1[ri] = e1; ti1[ri] = j1; td2[ri] = n2d; ti2[ri] = n2i;
            } else {
                if (better(e1, j1, td2[ri], ti2[ri])) { td2[ri] = e1; ti2[ri] = j1; }
            }
        }
    }
    // per-warp (code quarter) top-2 into smem merge arrays [cg][row]
    float* mg_d1 = (float*)(sm + B1_B);
    int*   mg_i1 = (int*)(sm + B1_B + 2048);
    float* mg_d2 = (float*)(sm + B1_B + 4096);
    int*   mg_i2 = (int*)(sm + B1_B + 6144);
    if ((lane & 3) == 0) {
#pragma unroll
        for (int ri = 0; ri < 4; ++ri) {
            int row = rg * 32 + (ri >> 1) * 16 + (ri & 1) * 8 + (lane >> 2);
            mg_d1[cg * MTILE + row] = td1[ri];
            mg_i1[cg * MTILE + row] = ti1[ri];
            mg_d2[cg * MTILE + row] = td2[ri];
            mg_i2[cg * MTILE + row] = ti2[ri];
        }
    }
    __syncthreads();

    // --- global top-2 over the 4 quarters, then exact fp32 refine ---
    float* stq = (float*)(sm + B0_B);   // 32 KB staging
    if (tid < MTILE) {
        const int m = tid;
        float d1 = mg_d1[m], d2v = mg_d2[m];
        int   i1 = mg_i1[m], i2v = mg_i2[m];
#pragma unroll
        for (int q = 1; q < 4; ++q) {
            float e1 = mg_d1[q * MTILE + m], e2 = mg_d2[q * MTILE + m];
            int   j1 = mg_i1[q * MTILE + m], j2 = mg_i2[q * MTILE + m];
            if (better(e1, j1, d1, i1)) {
                if (better(d1, i1, e2, j2)) { d2v = d1; i2v = i1; }
                else                         { d2v = e2; i2v = j2; }
                d1 = e1; i1 = j1;
            } else if (better(e1, j1, d2v, i2v)) {
                d2v = e1; i2v = j1;
            }
        }

        int ci[2] = {i1, i2v};
        float zz = zzs[m];
        float de[2];
#pragma unroll
        for (int t = 0; t < 2; ++t) {
            const float4* crow = (const float4*)(cb + (size_t)ci[t] * CDIM);
            float a = 0.f;
#pragma unroll
            for (int c4 = 0; c4 < CDIM / 4; ++c4) {
                float4 q = __ldg(&crow[c4]);
                a = fmaf(zs[(c4 * 4 + 0) * MTILE + m], q.x, a);
                a = fmaf(zs[(c4 * 4 + 1) * MTILE + m], q.y, a);
                a = fmaf(zs[(c4 * 4 + 2) * MTILE + m], q.z, a);
                a = fmaf(zs[(c4 * 4 + 3) * MTILE + m], q.w, a);
            }
            de[t] = fmaf(-2.0f, a, __fadd_rn(zz, __ldg(&g_ee[ci[t]])));
        }
        int bidx = ci[0];
        if (better(de[1], ci[1], de[0], ci[0])) bidx = ci[1];

        out[Z_ELEMS + (size_t)b * KTOT + k0v + m] = (float)bidx;
        atomicAdd(&g_hist[bidx], 1);

        const float4* crow = (const float4*)(cb + (size_t)bidx * CDIM);
        double lsum = 0.0;
#pragma unroll
        for (int c4 = 0; c4 < CDIM / 4; ++c4) {
            float4 q = __ldg(&crow[c4]);
            float zq[4] = {q.x, q.y, q.z, q.w};
#pragma unroll
            for (int u = 0; u < 4; ++u) {
                int c = c4 * 4 + u;
                float ze = zs[c * MTILE + m];
                float t  = __fsub_rn(zq[u], ze);
                stq[c * MTILE + m] = __fadd_rn(ze, t);
                lsum += (double)__fmul_rn(t, t);
            }
        }
#pragma unroll
        for (int o = 16; o > 0; o >>= 1)
            lsum += __shfl_down_sync(0xffffffffu, lsum, o);
        if ((tid & 31) == 0) sls[tid >> 5] = lsum;
    }
    __syncthreads();
    if (tid == 0)
        g_loss_part[blockIdx.x] = sls[0] + sls[1] + sls[2] + sls[3];

    // --- coalesced z_q_st store ---
    {
        float* ob = out + ((size_t)b * CDIM) * KTOT + k0v;
#pragma unroll
        for (int i = 0; i < 4; ++i) {
            int idx4 = tid + i * NTHREADS;
            int c = idx4 >> 5, v4 = idx4 & 31;
            *(float4*)(ob + (size_t)c * KTOT + v4 * 4) =
                *(const float4*)&stq[c * MTILE + v4 * 4];
        }
    }

    // --- fused finalize: last CTA reduces hist + loss ---
    __threadfence();
    if (tid == 0) {
        int old = atomicAdd(&g_count, 1);
        *flg = (old == NGRID - 1) ? 1 : 0;
    }
    __syncthreads();
    if (*flg) {
        __threadfence();   // acquire all blocks' writes
        float*  red_f = (float*)(sm + RED_B);
        double* red_d = (double*)(sm + RED_B + 2048);
        float ent = 0.f;
#pragma unroll
        for (int i = 0; i < NCODES / NTHREADS; ++i) {
            float p = (float)g_hist[tid + i * NTHREADS] * (1.0f / (float)N_VEC);
            ent += p * logf(p + 1e-10f);
        }
        red_f[tid] = ent;
        red_d[tid] = g_loss_part[tid];
        __syncthreads();
        for (int s = 256; s > 0; s >>= 1) {
            if (tid < s) { red_f[tid] += red_f[tid + s]; red_d[tid] += red_d[tid + s]; }
            __syncthreads();
        }
        if (tid == 0) {
            out[Z_ELEMS + N_VEC]     = (float)(red_d[0] * (1.25 / (double)Z_ELEMS));
            out[Z_ELEMS + N_VEC + 1] = expf(-red_f[0]);
            g_count = 0;   // reset for next graph replay
        }
    }
}

// ---------------------------------------------------------------------------
extern "C" void kernel_launch(void* const* d_in, const int* in_sizes, int n_in,
                              void* d_out, int out_size) {
    const float* z_e = (const float*)d_in[0];
    const float* cb  = (const float*)d_in[1];
    float* out = (float*)d_out;

    cudaFuncSetAttribute(vq_main, cudaFuncAttributeMaxDynamicSharedMemorySize,
                         SMEM_BYTES);

    vq_prep<<<8, 128>>>(cb);
    vq_main<<<NGRID, NTHREADS, SMEM_BYTES>>>(z_e, cb, out);
}

// round 10
// speedup vs baseline: 1.6487x; 1.1135x over previous
#include <cuda_runtime.h>
#include <cuda_bf16.h>
#include <math_constants.h>
#include <math.h>

#define CDIM     64
#define NCODES   1024
#define KTOT     2048
#define BATCH    32
#define N_VEC    (BATCH * KTOT)          // 65536
#define Z_ELEMS  (BATCH * CDIM * KTOT)   // 4194304
#define MTILE    128                     // vectors per CTA
#define KSPLIT   192                     // [zh|zh|zl] x [eh|el|eh]
#define NKS      12                      // k16 steps
#define CHUNKC   64                      // codes per chunk
#define NCHUNKS  (NCODES / CHUNKC)       // 16
#define NTHREADS 512
#define NGRID    512
#define APITCH   200                     // halves per row (192 + 8 pad)
#define BPITCH   200

// smem byte offsets
#define A_B      0                        // A halves image 128x200x2 = 51200
#define B0_B     51200                    // B chunk buf0 25600
#define B1_B     76800                    // B chunk buf1 25600
#define EES0_B   102400                   // 64 floats
#define EES1_B   102656                   // 64 floats
#define ZZS_B    102912                   // 128 floats
#define SLS_B    103424                   // 16 doubles
#define FLG_B    103552                   // flag int (+pad)
#define RED_B    103616                   // finalize: 512 f + 512 d = 6144
#define SMEM_BYTES 109760

// post-mainloop reuse:
#define ZS2_B    A_B                      // z fp32 reload 64x128 = 32768
#define MG_B     (A_B + 32768)            // merge arrays 4 x 2048 = 8192
#define STQ_B    B0_B                     // staging 32768 (spans B0+B1)

#define B_CHUNK_U4  1600                 // 25600 B / 16

__device__ float  g_ee[NCODES];
__device__ int    g_hist[NCODES];
__device__ double g_loss_part[NGRID];
__device__ int    g_count = 0;
__device__ __align__(16) unsigned short g_bh[NCODES * BPITCH];   // bf16 split codebook

// ---------------------------------------------------------------------------
__device__ __forceinline__ unsigned smem_u32(const void* p) {
    unsigned a;
    asm("{ .reg .u64 t; cvta.to.shared.u64 t, %1; cvt.u32.u64 %0, t; }"
        : "=r"(a) : "l"(p));
    return a;
}
__device__ __forceinline__ void ldsm4(unsigned& r0, unsigned& r1, unsigned& r2,
                                      unsigned& r3, unsigned addr) {
    asm volatile("ldmatrix.sync.aligned.m8n8.x4.shared.b16 {%0,%1,%2,%3}, [%4];"
                 : "=r"(r0), "=r"(r1), "=r"(r2), "=r"(r3) : "r"(addr));
}
__device__ __forceinline__ void mma16816(float* c, unsigned a0, unsigned a1,
                                         unsigned a2, unsigned a3,
                                         unsigned b0, unsigned b1) {
    asm volatile(
        "mma.sync.aligned.m16n8k16.row.col.f32.bf16.bf16.f32 "
        "{%0,%1,%2,%3}, {%4,%5,%6,%7}, {%8,%9}, {%0,%1,%2,%3};"
        : "+f"(c[0]), "+f"(c[1]), "+f"(c[2]), "+f"(c[3])
        : "r"(a0), "r"(a1), "r"(a2), "r"(a3), "r"(b0), "r"(b1));
}
__device__ __forceinline__ void cpa16(unsigned dst, const void* src) {
    asm volatile("cp.async.cg.shared.global [%0], [%1], 16;"
                 :: "r"(dst), "l"(src));
}
__device__ __forceinline__ void cpa4(unsigned dst, const void* src) {
    asm volatile("cp.async.ca.shared.global [%0], [%1], 4;"
                 :: "r"(dst), "l"(src));
}
__device__ __forceinline__ void cpa_commit() {
    asm volatile("cp.async.commit_group;" ::: "memory");
}
template <int N>
__device__ __forceinline__ void cpa_wait() {
    asm volatile("cp.async.wait_group %0;" :: "n"(N) : "memory");
}
__device__ __forceinline__ bool better(float da, int ia, float db, int ib) {
    return da < db || (da == db && ia < ib);
}

// ---------------------------------------------------------------------------
// prep: code norms (ascending-c), bf16 split codebook image, zero hist
// ---------------------------------------------------------------------------
__global__ void vq_prep(const float* __restrict__ cb) {
    int j = blockIdx.x * blockDim.x + threadIdx.x;
    if (j >= NCODES) return;
    const float4* row4 = (const float4*)(cb + j * CDIM);
    float r[CDIM];
#pragma unroll
    for (int q = 0; q < CDIM / 4; ++q) {
        float4 v = __ldg(&row4[q]);
        r[q * 4 + 0] = v.x; r[q * 4 + 1] = v.y;
        r[q * 4 + 2] = v.z; r[q * 4 + 3] = v.w;
    }
    unsigned short* img = g_bh + j * BPITCH;
    float s = 0.f;
#pragma unroll
    for (int c = 0; c < CDIM; ++c) {
        float e = r[c];
        s = __fadd_rn(s, __fmul_rn(e, e));
        __nv_bfloat16 eh = __float2bfloat16(e);
        __nv_bfloat16 el = __float2bfloat16(e - __bfloat162float(eh));
        img[c]       = __bfloat16_as_ushort(eh);
        img[64 + c]  = __bfloat16_as_ushort(el);
        img[128 + c] = __bfloat16_as_ushort(eh);
    }
#pragma unroll
    for (int c = KSPLIT; c < BPITCH; ++c) img[c] = 0;
    g_ee[j]   = s;
    g_hist[j] = 0;
}

// ---------------------------------------------------------------------------
// main: HMMA screen (warp = 32 rows x 16 codes), 64-code chunks double-buffered,
//       2 CTAs/SM, exact fp32 refine, fused last-CTA finalize.
// grid=512, block=512.
// ---------------------------------------------------------------------------
__global__ __launch_bounds__(NTHREADS, 2)
void vq_main(const float* __restrict__ z_e, const float* __restrict__ cb,
             float* __restrict__ out) {
    extern __shared__ char sm[];
    float*  zzs = (float*)(sm + ZZS_B);
    double* sls = (double*)(sm + SLS_B);
    int*    flg = (int*)(sm + FLG_B);
    const unsigned smem_base = smem_u32(sm);

    const int tid  = threadIdx.x;
    const int lane = tid & 31;
    const int w    = tid >> 5;
    const int rg   = w & 3;                 // rows 32rg..32rg+31
    const int cg   = w >> 2;                // codes 16cg..16cg+15
    const int b    = blockIdx.x >> 4;
    const int k0v  = (blockIdx.x & 15) * MTILE;

    // --- kick off B chunk 0 prefetch immediately ---
    {
        const uint4* src = (const uint4*)g_bh;
#pragma unroll
        for (int i = 0; i < 4; ++i) {
            int idx = tid + i * NTHREADS;
            if (idx < B_CHUNK_U4) cpa16(smem_base + B0_B + idx * 16, src + idx);
        }
        if (tid < CHUNKC) cpa4(smem_base + EES0_B + tid * 4, &g_ee[tid]);
        cpa_commit();
    }

    // --- per-vector norm (ascending-c) + A bf16-split image, from gmem ---
    const float* zbase = z_e + ((size_t)b * CDIM) * KTOT + k0v;
    if (tid < MTILE) {
        const int m = tid;
        unsigned short* arow = (unsigned short*)(sm + A_B) + m * APITCH;
        float s = 0.f;
#pragma unroll
        for (int c = 0; c < CDIM; ++c) {
            float z = __ldg(zbase + (size_t)c * KTOT + m);   // coalesced over m
            s = __fadd_rn(s, __fmul_rn(z, z));
            __nv_bfloat16 zh = __float2bfloat16(z);
            __nv_bfloat16 zl = __float2bfloat16(z - __bfloat162float(zh));
            arow[c]       = __bfloat16_as_ushort(zh);
            arow[64 + c]  = __bfloat16_as_ushort(zh);
            arow[128 + c] = __bfloat16_as_ushort(zl);
        }
        zzs[m] = s;
    }
    __syncthreads();

    // lane-invariant ldmatrix row components (validated mapping from R6)
    const int lrow = (lane & 7) + ((lane >> 3) & 1) * 8;   // row within 16
    const int lkof = (lane >> 4) * 8;                      // k half
    const unsigned a_base =
        smem_base + A_B + (unsigned)((rg * 32 + lrow) * APITCH + lkof) * 2;
    const unsigned b_row = (unsigned)((cg * 16 + lrow) * BPITCH + lkof) * 2;

    float zzr[4];
#pragma unroll
    for (int ri = 0; ri < 4; ++ri)
        zzr[ri] = zzs[rg * 32 + (ri >> 1) * 16 + (ri & 1) * 8 + (lane >> 2)];

    float td1[4], td2[4];
    int   ti1[4], ti2[4];
#pragma unroll
    for (int ri = 0; ri < 4; ++ri) {
        td1[ri] = CUDART_INF_F; td2[ri] = CUDART_INF_F;
        ti1[ri] = 0; ti2[ri] = 0;
    }

    for (int chunk = 0; chunk < NCHUNKS; ++chunk) {
        const int cur = chunk & 1;

        if (chunk < NCHUNKS - 1) {
            const uint4* src =
                (const uint4*)(g_bh + (size_t)(chunk + 1) * CHUNKC * BPITCH);
            unsigned dstb = smem_base + (cur ? B0_B : B1_B);
            unsigned dste = smem_base + (cur ? EES0_B : EES1_B);
#pragma unroll
            for (int i = 0; i < 4; ++i) {
                int idx = tid + i * NTHREADS;
                if (idx < B_CHUNK_U4) cpa16(dstb + idx * 16, src + idx);
            }
            if (tid < CHUNKC) cpa4(dste + tid * 4, &g_ee[(chunk + 1) * CHUNKC + tid]);
            cpa_commit();
            cpa_wait<1>();
        } else {
            cpa_wait<0>();
        }
        __syncthreads();

        const unsigned b_base = smem_base + (cur ? B1_B : B0_B) + b_row;
        const float* ees = (const float*)(sm + (cur ? EES1_B : EES0_B));

        float acc[2][2][4];
#pragma unroll
        for (int rf = 0; rf < 2; ++rf)
#pragma unroll
            for (int j = 0; j < 2; ++j)
#pragma unroll
                for (int r = 0; r < 4; ++r) acc[rf][j][r] = 0.f;

#pragma unroll
        for (int s = 0; s < NKS; ++s) {
            unsigned a0, a1, a2, a3, e0, e1, e2, e3, b0, b1, b2, b3;
            ldsm4(a0, a1, a2, a3, a_base + (unsigned)(s * 16) * 2);
            ldsm4(e0, e1, e2, e3, a_base + (unsigned)(16 * APITCH + s * 16) * 2);
            ldsm4(b0, b1, b2, b3, b_base + (unsigned)(s * 16) * 2);
            mma16816(acc[0][0], a0, a1, a2, a3, b0, b2);
            mma16816(acc[0][1], a0, a1, a2, a3, b1, b3);
            mma16816(acc[1][0], e0, e1, e2, e3, b0, b2);
            mma16816(acc[1][1], e0, e1, e2, e3, b1, b3);
        }

        // --- screen: d = zz + ee - 2*dot, per-thread top-2 per row ---
#pragma unroll
        for (int rf = 0; rf < 2; ++rf) {
#pragma unroll
            for (int j = 0; j < 2; ++j) {
                int e0i = cg * 16 + j * 8 + (lane & 3) * 2;
                int cg0 = chunk * CHUNKC + e0i;
                float ee0 = ees[e0i], ee1 = ees[e0i + 1];
#pragma unroll
                for (int r = 0; r < 4; ++r) {
                    float ee = (r & 1) ? ee1 : ee0;
                    int   cgi = cg0 + (r & 1);
                    int   ri = rf * 2 + (r >> 1);
                    float d  = fmaf(-2.0f, acc[rf][j][r], zzr[ri] + ee);
                    if (d < td1[ri]) {
                        td2[ri] = td1[ri]; ti2[ri] = ti1[ri];
                        td1[ri] = d;       ti1[ri] = cgi;
                    } else if (d < td2[ri]) {
                        td2[ri] = d; ti2[ri] = cgi;
                    }
                }
            }
        }
        __syncthreads();
    }

    // --- merge top-2 across the quad (lanes differing in bits 0,1) ---
#pragma unroll
    for (int xm = 1; xm <= 2; xm <<= 1) {
#pragma unroll
        for (int ri = 0; ri < 4; ++ri) {
            float e1 = __shfl_xor_sync(0xffffffffu, td1[ri], xm);
            int   j1 = __shfl_xor_sync(0xffffffffu, ti1[ri], xm);
            float e2 = __shfl_xor_sync(0xffffffffu, td2[ri], xm);
            int   j2 = __shfl_xor_sync(0xffffffffu, ti2[ri], xm);
            if (better(e1, j1, td1[ri], ti1[ri])) {
                float n2d; int n2i;
                if (better(td1[ri], ti1[ri], e2, j2)) { n2d = td1[ri]; n2i = ti1[ri]; }
                else                                   { n2d = e2;      n2i = j2; }
                td1[ri] = e1; ti1[ri] = j1; td2[ri] = n2d; ti2[ri] = n2i;
            } else {
                if (better(e1, j1, td2[ri], ti2[ri])) { td2[ri] = e1; ti2[ri] = j1; }
            }
        }
    }

    // per-warp (code quarter) top-2 into merge arrays [cg][row]
    float* mg_d1 = (float*)(sm + MG_B);
    int*   mg_i1 = (int*)(sm + MG_B + 2048);
    float* mg_d2 = (float*)(sm + MG_B + 4096);
    int*   mg_i2 = (int*)(sm + MG_B + 6144);
    if ((lane & 3) == 0) {
#pragma unroll
        for (int ri = 0; ri < 4; ++ri) {
            int row = rg * 32 + (ri >> 1) * 16 + (ri & 1) * 8 + (lane >> 2);
            mg_d1[cg * MTILE + row] = td1[ri];
            mg_i1[cg * MTILE + row] = ti1[ri];
            mg_d2[cg * MTILE + row] = td2[ri];
            mg_i2[cg * MTILE + row] = ti2[ri];
        }
    }

    // --- reload z tile fp32 into ZS2 (A image dead except MG region) ---
    __syncthreads();   // mainloop fully done before A region reuse
    float* zs2 = (float*)(sm + ZS2_B);
#pragma unroll
    for (int i = 0; i < 4; ++i) {
        int idx4 = tid + i * NTHREADS;       // 0..2047
        int c = idx4 >> 5, v4 = idx4 & 31;
        *(float4*)&zs2[c * MTILE + v4 * 4] =
            *(const float4*)(zbase + (size_t)c * KTOT + v4 * 4);
    }
    __syncthreads();

    // --- global top-2 over 4 quarters, exact fp32 refine, outputs ---
    float* stq = (float*)(sm + STQ_B);
    if (tid < MTILE) {
        const int m = tid;
        float d1 = mg_d1[m], d2v = mg_d2[m];
        int   i1 = mg_i1[m], i2v = mg_i2[m];
#pragma unroll
        for (int q = 1; q < 4; ++q) {
            float e1 = mg_d1[q * MTILE + m], e2 = mg_d2[q * MTILE + m];
            int   j1 = mg_i1[q * MTILE + m], j2 = mg_i2[q * MTILE + m];
            if (better(e1, j1, d1, i1)) {
                if (better(d1, i1, e2, j2)) { d2v = d1; i2v = i1; }
                else                         { d2v = e2; i2v = j2; }
                d1 = e1; i1 = j1;
            } else if (better(e1, j1, d2v, i2v)) {
                d2v = e1; i2v = j1;
            }
        }

        int ci[2] = {i1, i2v};
        float zz = zzs[m];
        float de[2];
#pragma unroll
        for (int t = 0; t < 2; ++t) {
            const float4* crow = (const float4*)(cb + (size_t)ci[t] * CDIM);
            float a = 0.f;
#pragma unroll
            for (int c4 = 0; c4 < CDIM / 4; ++c4) {
                float4 q = __ldg(&crow[c4]);
                a = fmaf(zs2[(c4 * 4 + 0) * MTILE + m], q.x, a);
                a = fmaf(zs2[(c4 * 4 + 1) * MTILE + m], q.y, a);
                a = fmaf(zs2[(c4 * 4 + 2) * MTILE + m], q.z, a);
                a = fmaf(zs2[(c4 * 4 + 3) * MTILE + m], q.w, a);
            }
            de[t] = fmaf(-2.0f, a, __fadd_rn(zz, __ldg(&g_ee[ci[t]])));
        }
        int bidx = ci[0];
        if (better(de[1], ci[1], de[0], ci[0])) bidx = ci[1];

        out[Z_ELEMS + (size_t)b * KTOT + k0v + m] = (float)bidx;
        atomicAdd(&g_hist[bidx], 1);

        const float4* crow = (const float4*)(cb + (size_t)bidx * CDIM);
        double lsum = 0.0;
#pragma unroll
        for (int c4 = 0; c4 < CDIM / 4; ++c4) {
            float4 q = __ldg(&crow[c4]);
            float zq[4] = {q.x, q.y, q.z, q.w};
#pragma unroll
            for (int u = 0; u < 4; ++u) {
                int c = c4 * 4 + u;
                float ze = zs2[c * MTILE + m];
                float t  = __fsub_rn(zq[u], ze);
                stq[c * MTILE + m] = __fadd_rn(ze, t);
                lsum += (double)__fmul_rn(t, t);
            }
        }
#pragma unroll
        for (int o = 16; o > 0; o >>= 1)
            lsum += __shfl_down_sync(0xffffffffu, lsum, o);
        if ((tid & 31) == 0) sls[tid >> 5] = lsum;
    }
    __syncthreads();
    if (tid == 0)
        g_loss_part[blockIdx.x] = sls[0] + sls[1] + sls[2] + sls[3];

    // --- coalesced z_q_st store ---
    {
        float* ob = out + ((size_t)b * CDIM) * KTOT + k0v;
#pragma unroll
        for (int i = 0; i < 4; ++i) {
            int idx4 = tid + i * NTHREADS;
            int c = idx4 >> 5, v4 = idx4 & 31;
            *(float4*)(ob + (size_t)c * KTOT + v4 * 4) =
                *(const float4*)&stq[c * MTILE + v4 * 4];
        }
    }

    // --- fused finalize: last CTA reduces hist + loss ---
    __threadfence();
    if (tid == 0) {
        int old = atomicAdd(&g_count, 1);
        *flg = (old == NGRID - 1) ? 1 : 0;
    }
    __syncthreads();
    if (*flg) {
        __threadfence();
        float*  red_f = (float*)(sm + RED_B);
        double* red_d = (double*)(sm + RED_B + 2048);
        float ent = 0.f;
#pragma unroll
        for (int i = 0; i < NCODES / NTHREADS; ++i) {
            float p = (float)g_hist[tid + i * NTHREADS] * (1.0f / (float)N_VEC);
            ent += p * logf(p + 1e-10f);
        }
        red_f[tid] = ent;
        red_d[tid] = g_loss_part[tid];
        __syncthreads();
        for (int s = 256; s > 0; s >>= 1) {
            if (tid < s) { red_f[tid] += red_f[tid + s]; red_d[tid] += red_d[tid + s]; }
            __syncthreads();
        }
        if (tid == 0) {
            out[Z_ELEMS + N_VEC]     = (float)(red_d[0] * (1.25 / (double)Z_ELEMS));
            out[Z_ELEMS + N_VEC + 1] = expf(-red_f[0]);
            g_count = 0;   // reset for next graph replay
        }
    }
}

// ---------------------------------------------------------------------------
extern "C" void kernel_launch(void* const* d_in, const int* in_sizes, int n_in,
                              void* d_out, int out_size) {
    const float* z_e = (const float*)d_in[0];
    const float* cb  = (const float*)d_in[1];
    float* out = (float*)d_out;

    cudaFuncSetAttribute(vq_main, cudaFuncAttributeMaxDynamicSharedMemorySize,
                         SMEM_BYTES);

    vq_prep<<<8, 128>>>(cb);
    vq_main<<<NGRID, NTHREADS, SMEM_BYTES>>>(z_e, cb, out);
}